// round 14
// baseline (speedup 1.0000x reference)
#include <cuda_runtime.h>
#include <cuda_fp16.h>
#include <math.h>
#include <stdint.h>

#define BATCH   8
#define SEQLEN  1024
#define NTOK    (BATCH*SEQLEN)     // 8192
#define DMODEL  512
#define DSTATE  64
#define DINNER  1024
#define NHEADS  16
#define HEADDIM 64
#define DINPROJ 2192
#define DINPROJ_PAD 2304
#define CONVDIM 1152
#define DFFN    2048
#define BETA    0.5f
#define CHUNK   64
#define NCHUNK  16

// ---------------- scratch ----------------------------------------------------
__device__ __half g_zxh[NTOK*DINPROJ];
__device__ __half g_xc0h[NTOK*CONVDIM];
__device__ __half g_xc1h[NTOK*CONVDIM];
__device__ float  g_dt [NTOK*NHEADS];
__device__ float  g_ldA[NTOK*NHEADS];
__device__ float  g_y0 [NTOK*DINNER];
__device__ float  g_y1 [NTOK*DINNER];
__device__ float  g_O  [NTOK*DMODEL];
__device__ float  g_Xln[NTOK*DMODEL];
__device__ float  g_H2 [NTOK*DMODEL];
__device__ float  g_cum[2*BATCH*NHEADS*SEQLEN];
__device__ float  g_L  [2*BATCH*NHEADS*NCHUNK*HEADDIM*DSTATE];
__device__ float  g_Hi [2*BATCH*NHEADS*NCHUNK*HEADDIM*DSTATE];
// fp16 operands
__device__ __half g_emb_h[NTOK*DMODEL];
__device__ __half g_Gh   [NTOK*DINNER];
__device__ __half g_Xh   [NTOK*DMODEL];
__device__ __half g_H1h  [NTOK*DFFN];
__device__ __half g_win_h [DINPROJ_PAD*DMODEL];
__device__ __half g_wout_h[DMODEL*DINNER];
__device__ __half g_w1_h  [DFFN*DMODEL];
__device__ __half g_w2_h  [DMODEL*DFFN];

// ---------------- helpers ----------------------------------------------------
__device__ __forceinline__ float siluf(float v) {
    return v * __frcp_rn(1.0f + __expf(-v));
}
__device__ __forceinline__ float geluf(float v) { return 0.5f * v * (1.0f + erff(v * 0.70710678118654752f)); }
__device__ __forceinline__ float softplusf(float x) { return fmaxf(x, 0.0f) + log1pf(expf(-fabsf(x))); }

__device__ __forceinline__ void cpasync16(uint32_t saddr, const void* gptr) {
    asm volatile("cp.async.cg.shared.global [%0], [%1], 16;\n" :: "r"(saddr), "l"(gptr));
}
__device__ __forceinline__ void cp_commit() { asm volatile("cp.async.commit_group;\n"); }
__device__ __forceinline__ void cp_wait0()  { asm volatile("cp.async.wait_group 0;\n"); }
__device__ __forceinline__ void cp_wait1()  { asm volatile("cp.async.wait_group 1;\n"); }
__device__ __forceinline__ void cp_wait2()  { asm volatile("cp.async.wait_group 2;\n"); }

__device__ __forceinline__ void ldsm_x4(uint32_t& r0, uint32_t& r1, uint32_t& r2, uint32_t& r3,
                                        uint32_t saddr) {
    asm volatile("ldmatrix.sync.aligned.m8n8.x4.shared.b16 {%0,%1,%2,%3}, [%4];"
        : "=r"(r0), "=r"(r1), "=r"(r2), "=r"(r3) : "r"(saddr));
}

#define MMA16816(d0,d1,d2,d3,a0,a1,a2,a3,b0,b1) \
    asm volatile( \
        "mma.sync.aligned.m16n8k16.row.col.f32.f16.f16.f32 " \
        "{%0,%1,%2,%3}, {%4,%5,%6,%7}, {%8,%9}, {%0,%1,%2,%3};" \
        : "+f"(d0), "+f"(d1), "+f"(d2), "+f"(d3) \
        : "r"(a0), "r"(a1), "r"(a2), "r"(a3), "r"(b0), "r"(b1))

__device__ __forceinline__ float blockReduceSum(float v, float* sdata) {
    int tid = threadIdx.x;
    sdata[tid] = v; __syncthreads();
    for (int s = blockDim.x >> 1; s > 0; s >>= 1) {
        if (tid < s) sdata[tid] += sdata[tid + s];
        __syncthreads();
    }
    float r = sdata[0]; __syncthreads();
    return r;
}
__device__ __forceinline__ uint32_t pack2h(float x, float y) {
    __half2 h = __float22half2_rn(make_float2(x, y));
    return *(uint32_t*)&h;
}

// ---------------- fused fp32 -> fp16 converter (one launch) ------------------
#define Q_EMB  (NTOK*DMODEL/4)
#define Q_WIN  (DINPROJ_PAD*DMODEL/4)
#define Q_WOUT (DMODEL*DINNER/4)
#define Q_W1   (DFFN*DMODEL/4)
#define Q_W2   (DMODEL*DFFN/4)
#define Q_TOT  (Q_EMB+Q_WIN+Q_WOUT+Q_W1+Q_W2)

__global__ void cvt_all_kernel(const float* __restrict__ emb,
                               const float* __restrict__ win,
                               const float* __restrict__ wout,
                               const float* __restrict__ w1,
                               const float* __restrict__ w2)
{
    int q = blockIdx.x * blockDim.x + threadIdx.x;
    if (q >= Q_TOT) return;
    const float* src;
    __half* dst;
    int idx;
    if (q < Q_EMB)                       { src = emb;  dst = g_emb_h;  idx = q; }
    else if (q < Q_EMB+Q_WIN)            { src = win;  dst = g_win_h;  idx = q - Q_EMB;
        int row = (idx * 4) / DMODEL;
        if (row >= DINPROJ) {
            __half2* d = (__half2*)&dst[idx * 4];
            d[0] = __half2(__float2half(0.f), __float2half(0.f));
            d[1] = __half2(__float2half(0.f), __float2half(0.f));
            return;
        }
    }
    else if (q < Q_EMB+Q_WIN+Q_WOUT)     { src = wout; dst = g_wout_h; idx = q - (Q_EMB+Q_WIN); }
    else if (q < Q_EMB+Q_WIN+Q_WOUT+Q_W1){ src = w1;   dst = g_w1_h;   idx = q - (Q_EMB+Q_WIN+Q_WOUT); }
    else                                 { src = w2;   dst = g_w2_h;   idx = q - (Q_EMB+Q_WIN+Q_WOUT+Q_W1); }

    float4 v = *(const float4*)&src[idx * 4];
    __half2* d = (__half2*)&dst[idx * 4];
    d[0] = __float22half2_rn(make_float2(v.x, v.y));
    d[1] = __float22half2_rn(make_float2(v.z, v.w));
}

// ---------------- FP16 GEMM 128x128 (cp.async 4-stage) -----------------------
#define LDH 20
#define TILE_W (128 * LDH)
#define GEMM_SMEM (8 * TILE_W * 4)

template<int EPI, int OUTH>
__global__ __launch_bounds__(256, 2)
void h16gemm(const __half* __restrict__ A, const __half* __restrict__ B,
             const float* __restrict__ bias, void* __restrict__ Cv,
             int M, int N, int K)
{
    extern __shared__ uint32_t smemu[];
    uint32_t* AsB = smemu;
    uint32_t* BsB = smemu + 4 * TILE_W;

    const int tid = threadIdx.x;
    const int m0 = blockIdx.y * 128;
    const int n0 = blockIdx.x * 128;

    const int w    = tid >> 5;
    const int lane = tid & 31;
    const int wm   = (w >> 2) * 64;
    const int wn   = (w & 3) * 32;
    const int gr   = lane >> 2;
    const int gcw  = lane & 3;

    const int row0 = tid >> 2;
    const int c0   = tid & 3;

    uint32_t asb = (uint32_t)__cvta_generic_to_shared(AsB);
    uint32_t bsb = (uint32_t)__cvta_generic_to_shared(BsB);
    const uint32_t stg = TILE_W * 4;

    const uint32_t a_lane = (uint32_t)(((lane & 7) + ((lane >> 3) & 1) * 8) * 80
                                       + (lane >> 4) * 16);
    const uint32_t b_lane = (uint32_t)((lane & 15) * 80 + (lane >> 4) * 16);

    float acc[4][4][4];
    #pragma unroll
    for (int i = 0; i < 4; ++i)
        #pragma unroll
        for (int j = 0; j < 4; ++j)
            #pragma unroll
            for (int r = 0; r < 4; ++r) acc[i][j][r] = 0.0f;

    const int KT = K / 32;

    #pragma unroll
    for (int t = 0; t < 3; ++t) {
        if (t < KT) {
            size_t koff = (size_t)t * 32 + c0 * 8;
            #pragma unroll
            for (int i = 0; i < 2; ++i) {
                int row = row0 + i * 64;
                uint32_t doff = (uint32_t)t * stg + (uint32_t)(row * 80 + c0 * 16);
                cpasync16(asb + doff, A + (size_t)(m0 + row) * K + koff);
                cpasync16(bsb + doff, B + (size_t)(n0 + row) * K + koff);
            }
            cp_commit();
        }
    }

    for (int kt = 0; kt < KT; ++kt) {
        int rem = KT - 1 - kt;
        if (rem >= 2)      cp_wait2();
        else if (rem == 1) cp_wait1();
        else               cp_wait0();
        __syncthreads();

        if (kt + 3 < KT) {
            int nb = (kt + 3) & 3;
            size_t koff = (size_t)(kt + 3) * 32 + c0 * 8;
            #pragma unroll
            for (int i = 0; i < 2; ++i) {
                int row = row0 + i * 64;
                uint32_t doff = (uint32_t)nb * stg + (uint32_t)(row * 80 + c0 * 16);
                cpasync16(asb + doff, A + (size_t)(m0 + row) * K + koff);
                cpasync16(bsb + doff, B + (size_t)(n0 + row) * K + koff);
            }
            cp_commit();
        }

        const int cur = kt & 3;
        const uint32_t as_st = asb + (uint32_t)cur * stg;
        const uint32_t bs_st = bsb + (uint32_t)cur * stg;
        #pragma unroll
        for (int kk = 0; kk < 2; ++kk) {
            const uint32_t kb = (uint32_t)(kk * 32);
            uint32_t af[4][4];
            #pragma unroll
            for (int mi = 0; mi < 4; ++mi) {
                uint32_t sa = as_st + (uint32_t)((wm + mi * 16) * 80) + kb + a_lane;
                ldsm_x4(af[mi][0], af[mi][1], af[mi][2], af[mi][3], sa);
            }
            uint32_t bf[4][2];
            #pragma unroll
            for (int np = 0; np < 2; ++np) {
                uint32_t sb = bs_st + (uint32_t)((wn + np * 16) * 80) + kb + b_lane;
                ldsm_x4(bf[np*2][0], bf[np*2+1][0], bf[np*2][1], bf[np*2+1][1], sb);
            }
            #pragma unroll
            for (int mi = 0; mi < 4; ++mi)
                #pragma unroll
                for (int ni = 0; ni < 4; ++ni)
                    MMA16816(acc[mi][ni][0], acc[mi][ni][1], acc[mi][ni][2], acc[mi][ni][3],
                             af[mi][0], af[mi][1], af[mi][2], af[mi][3],
                             bf[ni][0], bf[ni][1]);
        }
    }

    float* Cf = (float*)Cv;
    __half* Ch = (__half*)Cv;
    #pragma unroll
    for (int mi = 0; mi < 4; ++mi) {
        int r = m0 + wm + mi * 16 + gr;
        #pragma unroll
        for (int ni = 0; ni < 4; ++ni) {
            int cb = n0 + wn + ni * 8 + 2 * gcw;
            #pragma unroll
            for (int half = 0; half < 2; ++half) {
                int rr = r + half * 8;
                float v0 = acc[mi][ni][half * 2 + 0];
                float v1 = acc[mi][ni][half * 2 + 1];
                if (cb < N) {
                    if (EPI >= 1) v0 += bias[cb];
                    if (EPI == 2) v0 = geluf(v0);
                    if (OUTH) Ch[(size_t)rr * N + cb] = __float2half_rn(v0);
                    else      Cf[(size_t)rr * N + cb] = v0;
                }
                if (cb + 1 < N) {
                    if (EPI >= 1) v1 += bias[cb + 1];
                    if (EPI == 2) v1 = geluf(v1);
                    if (OUTH) Ch[(size_t)rr * N + cb + 1] = __float2half_rn(v1);
                    else      Cf[(size_t)rr * N + cb + 1] = v1;
                }
            }
        }
    }
}

// ---------------- FP16 GEMM 128x256 (cp.async 3-stage, 64x64 warp tile) ------
#define TILE_WA (128 * LDH)           // 2560 words
#define TILE_WB (256 * LDH)           // 5120 words
#define GEMM256_SMEM (3 * (TILE_WA + TILE_WB) * 4)   // 92160 B

template<int EPI, int OUTH>
__global__ __launch_bounds__(256, 1)
void h16gemm256(const __half* __restrict__ A, const __half* __restrict__ B,
                const float* __restrict__ bias, void* __restrict__ Cv,
                int M, int N, int K)
{
    extern __shared__ uint32_t smemu[];
    uint32_t* AsB = smemu;                      // 3 stages of A
    uint32_t* BsB = smemu + 3 * TILE_WA;        // 3 stages of B

    const int tid = threadIdx.x;
    const int m0 = blockIdx.y * 128;
    const int n0 = blockIdx.x * 256;

    const int w    = tid >> 5;
    const int lane = tid & 31;
    const int wm   = (w >> 2) * 64;     // 0 / 64
    const int wn   = (w & 3) * 64;      // 0..192
    const int gr   = lane >> 2;
    const int gcw  = lane & 3;

    const int row0 = tid >> 2;          // 0..63
    const int c0   = tid & 3;

    uint32_t asb = (uint32_t)__cvta_generic_to_shared(AsB);
    uint32_t bsb = (uint32_t)__cvta_generic_to_shared(BsB);
    const uint32_t stgA = TILE_WA * 4;
    const uint32_t stgB = TILE_WB * 4;

    const uint32_t a_lane = (uint32_t)(((lane & 7) + ((lane >> 3) & 1) * 8) * 80
                                       + (lane >> 4) * 16);
    const uint32_t b_lane = (uint32_t)((lane & 15) * 80 + (lane >> 4) * 16);

    float acc[4][8][4];
    #pragma unroll
    for (int i = 0; i < 4; ++i)
        #pragma unroll
        for (int j = 0; j < 8; ++j)
            #pragma unroll
            for (int r = 0; r < 4; ++r) acc[i][j][r] = 0.0f;

    const int KT = K / 32;

    // prologue: stages 0,1
    #pragma unroll
    for (int t = 0; t < 2; ++t) {
        if (t < KT) {
            size_t koff = (size_t)t * 32 + c0 * 8;
            #pragma unroll
            for (int i = 0; i < 2; ++i) {
                int row = row0 + i * 64;
                uint32_t doff = (uint32_t)t * stgA + (uint32_t)(row * 80 + c0 * 16);
                cpasync16(asb + doff, A + (size_t)(m0 + row) * K + koff);
            }
            #pragma unroll
            for (int i = 0; i < 4; ++i) {
                int row = row0 + i * 64;
                uint32_t doff = (uint32_t)t * stgB + (uint32_t)(row * 80 + c0 * 16);
                cpasync16(bsb + doff, B + (size_t)(n0 + row) * K + koff);
            }
            cp_commit();
        }
    }

    int cur = 0;
    for (int kt = 0; kt < KT; ++kt) {
        if (kt + 1 < KT) cp_wait1(); else cp_wait0();
        __syncthreads();

        if (kt + 2 < KT) {
            int nb = cur + 2; if (nb >= 3) nb -= 3;
            size_t koff = (size_t)(kt + 2) * 32 + c0 * 8;
            #pragma unroll
            for (int i = 0; i < 2; ++i) {
                int row = row0 + i * 64;
                uint32_t doff = (uint32_t)nb * stgA + (uint32_t)(row * 80 + c0 * 16);
                cpasync16(asb + doff, A + (size_t)(m0 + row) * K + koff);
            }
            #pragma unroll
            for (int i = 0; i < 4; ++i) {
                int row = row0 + i * 64;
                uint32_t doff = (uint32_t)nb * stgB + (uint32_t)(row * 80 + c0 * 16);
                cpasync16(bsb + doff, B + (size_t)(n0 + row) * K + koff);
            }
            cp_commit();
        }

        const uint32_t as_st = asb + (uint32_t)cur * stgA;
        const uint32_t bs_st = bsb + (uint32_t)cur * stgB;
        #pragma unroll
        for (int kk = 0; kk < 2; ++kk) {
            const uint32_t kb = (uint32_t)(kk * 32);
            uint32_t af[4][4];
            #pragma unroll
            for (int mi = 0; mi < 4; ++mi) {
                uint32_t sa = as_st + (uint32_t)((wm + mi * 16) * 80) + kb + a_lane;
                ldsm_x4(af[mi][0], af[mi][1], af[mi][2], af[mi][3], sa);
            }
            uint32_t bf[8][2];
            #pragma unroll
            for (int np = 0; np < 4; ++np) {
                uint32_t sb = bs_st + (uint32_t)((wn + np * 16) * 80) + kb + b_lane;
                ldsm_x4(bf[np*2][0], bf[np*2+1][0], bf[np*2][1], bf[np*2+1][1], sb);
            }
            #pragma unroll
            for (int mi = 0; mi < 4; ++mi)
                #pragma unroll
                for (int ni = 0; ni < 8; ++ni)
                    MMA16816(acc[mi][ni][0], acc[mi][ni][1], acc[mi][ni][2], acc[mi][ni][3],
                             af[mi][0], af[mi][1], af[mi][2], af[mi][3],
                             bf[ni][0], bf[ni][1]);
        }
        __syncthreads();
        if (++cur == 3) cur = 0;
    }

    float* Cf = (float*)Cv;
    __half* Ch = (__half*)Cv;
    #pragma unroll
    for (int mi = 0; mi < 4; ++mi) {
        int r = m0 + wm + mi * 16 + gr;
        #pragma unroll
        for (int ni = 0; ni < 8; ++ni) {
            int cb = n0 + wn + ni * 8 + 2 * gcw;
            #pragma unroll
            for (int half = 0; half < 2; ++half) {
                int rr = r + half * 8;
                float v0 = acc[mi][ni][half * 2 + 0];
                float v1 = acc[mi][ni][half * 2 + 1];
                if (cb < N) {
                    if (EPI >= 1) v0 += bias[cb];
                    if (EPI == 2) v0 = geluf(v0);
                    if (OUTH) Ch[(size_t)rr * N + cb] = __float2half_rn(v0);
                    else      Cf[(size_t)rr * N + cb] = v0;
                }
                if (cb + 1 < N) {
                    if (EPI >= 1) v1 += bias[cb + 1];
                    if (EPI == 2) v1 = geluf(v1);
                    if (OUTH) Ch[(size_t)rr * N + cb + 1] = __float2half_rn(v1);
                    else      Cf[(size_t)rr * N + cb + 1] = v1;
                }
            }
        }
    }
}

// ---------------- conv + silu -> fp16 (reads fp16 zx) ------------------------
__global__ void conv_silu_kernel(const float* __restrict__ conv_w,
                                 const float* __restrict__ conv_b)
{
    int e = blockIdx.x * blockDim.x + threadIdx.x;
    const int C4 = CONVDIM / 4;
    const int total = 2 * NTOK * C4;
    if (e >= total) return;
    int dir = e / (NTOK * C4);
    int rem = e - dir * (NTOK * C4);
    int bt = rem / C4;
    int c4 = rem % C4;
    int b = bt / SEQLEN;
    int t = bt % SEQLEN;
    int c = c4 * 4;

    float4 w0 = *(const float4*)&conv_w[(c + 0) * 4];
    float4 w1 = *(const float4*)&conv_w[(c + 1) * 4];
    float4 w2 = *(const float4*)&conv_w[(c + 2) * 4];
    float4 w3 = *(const float4*)&conv_w[(c + 3) * 4];
    float4 acc = *(const float4*)&conv_b[c];

    float wt0[4] = {w0.x, w0.y, w0.z, w0.w};
    float wt1[4] = {w1.x, w1.y, w1.z, w1.w};
    float wt2[4] = {w2.x, w2.y, w2.z, w2.w};
    float wt3[4] = {w3.x, w3.y, w3.z, w3.w};

    #pragma unroll
    for (int k = 0; k < 4; ++k) {
        int tp = t - 3 + k;
        if (tp >= 0) {
            int s = dir ? (SEQLEN - 1 - tp) : tp;
            uint2 raw = *(const uint2*)&g_zxh[(size_t)(b * SEQLEN + s) * DINPROJ + DINNER + c];
            float2 v01 = __half22float2(*(__half2*)&raw.x);
            float2 v23 = __half22float2(*(__half2*)&raw.y);
            acc.x = fmaf(wt0[k], v01.x, acc.x);
            acc.y = fmaf(wt1[k], v01.y, acc.y);
            acc.z = fmaf(wt2[k], v23.x, acc.z);
            acc.w = fmaf(wt3[k], v23.y, acc.w);
        }
    }
    uint2 o;
    o.x = pack2h(siluf(acc.x), siluf(acc.y));
    o.y = pack2h(siluf(acc.z), siluf(acc.w));
    __half* out = dir ? g_xc1h : g_xc0h;
    *(uint2*)&out[(size_t)bt * CONVDIM + c] = o;
}

// ---------------- dt = softplus(raw + bias); ldA = dt*A ---------------------
__global__ void dt_kernel(const float* __restrict__ dt_bias,
                          const float* __restrict__ A_log)
{
    int e = blockIdx.x * blockDim.x + threadIdx.x;
    if (e >= NTOK * NHEADS) return;
    int bt = e / NHEADS;
    int h  = e % NHEADS;
    float x = __half2float(g_zxh[(size_t)bt * DINPROJ + (DINNER + CONVDIM) + h]) + dt_bias[h];
    float dtv = softplusf(x);
    g_dt[e]  = dtv;
    g_ldA[e] = dtv * (-expf(A_log[h]));
}

// ---------------- SSD pass A: chunk GEMMs ------------------------------------
#define LDW 36

__global__ __launch_bounds__(128)
void ssd_chunk_mma_kernel(const float* __restrict__ Dp)
{
    __shared__ uint32_t Ck [64 * LDW];
    __shared__ uint32_t Bk [64 * LDW];
    __shared__ uint32_t Xt [64 * LDW];
    __shared__ uint32_t Btw[64 * LDW];
    __shared__ uint32_t Wsm[64 * LDW];
    __shared__ float sdt[64];
    __shared__ float slc[64];

    int blk   = blockIdx.x;
    int chunk = blk & 15;
    int h     = (blk >> 4) & 15;
    int b     = (blk >> 8) & 7;
    int dir   = blk >> 11;
    const int tid  = threadIdx.x;
    const int w    = tid >> 5;
    const int lane = tid & 31;
    const int gr   = lane >> 2;
    const int gcw  = lane & 3;
    const int wm   = w * 16;

    const __half* xch = dir ? g_xc1h : g_xc0h;
    float* yout = dir ? g_y1 : g_y0;
    const size_t hb = (size_t)(dir * BATCH + b) * NHEADS + h;
    const int t0 = chunk * CHUNK;

    if (tid < 64) {
        int t = t0 + tid;
        int s = dir ? (SEQLEN - 1 - t) : t;
        size_t de = (size_t)(b * SEQLEN + s) * NHEADS + h;
        sdt[tid] = g_dt[de];
        slc[tid] = g_ldA[de];
    }
    __syncthreads();
    #pragma unroll
    for (int off = 1; off < 64; off <<= 1) {
        float add = 0.0f;
        if (tid < 64 && tid >= off) add = slc[tid - off];
        __syncthreads();
        if (tid < 64) slc[tid] += add;
        __syncthreads();
    }
    if (tid < 64) g_cum[hb * SEQLEN + t0 + tid] = __expf(slc[tid]);
    __syncthreads();
    const float lcLast = slc[63];

    __half* XtH  = (__half*)Xt;
    __half* BtwH = (__half*)Btw;

    #pragma unroll
    for (int i = 0; i < 8; ++i) {
        int id = tid + i * 128;
        int row = id >> 4;
        int f4  = id & 15;
        size_t base = (size_t)(b * SEQLEN + t0 + row) * CONVDIM + DINNER;
        uint2 vb = *(const uint2*)&xch[base + f4 * 4];
        uint2 vc = *(const uint2*)&xch[base + DSTATE + f4 * 4];
        Bk[row * LDW + f4 * 2 + 0] = vb.x;
        Bk[row * LDW + f4 * 2 + 1] = vb.y;
        Ck[row * LDW + f4 * 2 + 0] = vc.x;
        Ck[row * LDW + f4 * 2 + 1] = vc.y;
    }
    #pragma unroll
    for (int i = 0; i < 8; ++i) {
        int id = tid + i * 128;
        int srow = id >> 4;
        int f4   = id & 15;
        size_t base = (size_t)(b * SEQLEN + t0 + srow) * CONVDIM;
        float w2f = sdt[srow] * __expf(lcLast - slc[srow]);
        __half2 w2h = __float2half2_rn(w2f);

        uint2 vx = *(const uint2*)&xch[base + h * HEADDIM + f4 * 4];
        __half2 x01 = *(__half2*)&vx.x;
        __half2 x23 = *(__half2*)&vx.y;
        XtH[(f4*4+0) * 72 + srow] = __low2half(x01);
        XtH[(f4*4+1) * 72 + srow] = __high2half(x01);
        XtH[(f4*4+2) * 72 + srow] = __low2half(x23);
        XtH[(f4*4+3) * 72 + srow] = __high2half(x23);

        uint2 vb = *(const uint2*)&xch[base + DINNER + f4 * 4];
        __half2 b01 = __hmul2(*(__half2*)&vb.x, w2h);
        __half2 b23 = __hmul2(*(__half2*)&vb.y, w2h);
        BtwH[(f4*4+0) * 72 + srow] = __low2half(b01);
        BtwH[(f4*4+1) * 72 + srow] = __high2half(b01);
        BtwH[(f4*4+2) * 72 + srow] = __low2half(b23);
        BtwH[(f4*4+3) * 72 + srow] = __high2half(b23);
    }
    __syncthreads();

    // GEMM 1: G = Ck @ Bk^T
    {
        float acc[8][4];
        #pragma unroll
        for (int j = 0; j < 8; ++j)
            #pragma unroll
            for (int r = 0; r < 4; ++r) acc[j][r] = 0.0f;

        #pragma unroll
        for (int kk = 0; kk < 4; ++kk) {
            const int kw = kk * 8;
            uint32_t a0 = Ck[(wm + gr) * LDW + kw + gcw];
            uint32_t a1 = Ck[(wm + 8 + gr) * LDW + kw + gcw];
            uint32_t a2 = Ck[(wm + gr) * LDW + kw + gcw + 4];
            uint32_t a3 = Ck[(wm + 8 + gr) * LDW + kw + gcw + 4];
            #pragma unroll
            for (int ni = 0; ni < 8; ++ni) {
                uint32_t b0 = Bk[(ni * 8 + gr) * LDW + kw + gcw];
                uint32_t b1 = Bk[(ni * 8 + gr) * LDW + kw + gcw + 4];
                MMA16816(acc[ni][0], acc[ni][1], acc[ni][2], acc[ni][3],
                         a0, a1, a2, a3, b0, b1);
            }
        }

        int t_r0 = wm + gr, t_r1 = wm + gr + 8;
        float lt0 = slc[t_r0], lt1 = slc[t_r1];
        #pragma unroll
        for (int ni = 0; ni < 8; ++ni) {
            int s0 = ni * 8 + 2 * gcw;
            int s1 = s0 + 1;
            float ls0 = slc[s0], ls1 = slc[s1];
            float d0 = sdt[s0],  d1 = sdt[s1];
            float w00 = (s0 <= t_r0) ? __expf(lt0 - ls0) * d0 * acc[ni][0] : 0.0f;
            float w01 = (s1 <= t_r0) ? __expf(lt0 - ls1) * d1 * acc[ni][1] : 0.0f;
            float w10 = (s0 <= t_r1) ? __expf(lt1 - ls0) * d0 * acc[ni][2] : 0.0f;
            float w11 = (s1 <= t_r1) ? __expf(lt1 - ls1) * d1 * acc[ni][3] : 0.0f;
            Wsm[t_r0 * LDW + ni * 4 + gcw] = pack2h(w00, w01);
            Wsm[t_r1 * LDW + ni * 4 + gcw] = pack2h(w10, w11);
        }
    }
    __syncthreads();

    // GEMM 2: Y = W @ X
    {
        float acc[8][4];
        #pragma unroll
        for (int j = 0; j < 8; ++j)
            #pragma unroll
            for (int r = 0; r < 4; ++r) acc[j][r] = 0.0f;

        #pragma unroll
        for (int kk = 0; kk < 4; ++kk) {
            const int kw = kk * 8;
            uint32_t a0 = Wsm[(wm + gr) * LDW + kw + gcw];
            uint32_t a1 = Wsm[(wm + 8 + gr) * LDW + kw + gcw];
            uint32_t a2 = Wsm[(wm + gr) * LDW + kw + gcw + 4];
            uint32_t a3 = Wsm[(wm + 8 + gr) * LDW + kw + gcw + 4];
            #pragma unroll
            for (int ni = 0; ni < 8; ++ni) {
                uint32_t b0 = Xt[(ni * 8 + gr) * LDW + kw + gcw];
                uint32_t b1 = Xt[(ni * 8 + gr) * LDW + kw + gcw + 4];
                MMA16816(acc[ni][0], acc[ni][1], acc[ni][2], acc[ni][3],
                         a0, a1, a2, a3, b0, b1);
            }
        }

        float Dh = Dp[h];
        int t_r0 = wm + gr, t_r1 = t_r0 + 8;
        size_t yb0 = (size_t)(b * SEQLEN + t0 + t_r0) * DINNER + h * HEADDIM;
        size_t yb1 = (size_t)(b * SEQLEN + t0 + t_r1) * DINNER + h * HEADDIM;
        #pragma unroll
        for (int ni = 0; ni < 8; ++ni) {
            int p0 = ni * 8 + 2 * gcw;
            float x00 = __half2float(XtH[p0 * 72 + t_r0]);
            float x01 = __half2float(XtH[(p0+1) * 72 + t_r0]);
            float x10 = __half2float(XtH[p0 * 72 + t_r1]);
            float x11 = __half2float(XtH[(p0+1) * 72 + t_r1]);
            yout[yb0 + p0]     = acc[ni][0] + Dh * x00;
            yout[yb0 + p0 + 1] = acc[ni][1] + Dh * x01;
            yout[yb1 + p0]     = acc[ni][2] + Dh * x10;
            yout[yb1 + p0 + 1] = acc[ni][3] + Dh * x11;
        }
    }

    // GEMM 3: S[p][n] = Xt[p][s] @ Btw[n][s]^T
    {
        float acc[8][4];
        #pragma unroll
        for (int j = 0; j < 8; ++j)
            #pragma unroll
            for (int r = 0; r < 4; ++r) acc[j][r] = 0.0f;

        #pragma unroll
        for (int kk = 0; kk < 4; ++kk) {
            const int kw = kk * 8;
            uint32_t a0 = Xt[(wm + gr) * LDW + kw + gcw];
            uint32_t a1 = Xt[(wm + 8 + gr) * LDW + kw + gcw];
            uint32_t a2 = Xt[(wm + gr) * LDW + kw + gcw + 4];
            uint32_t a3 = Xt[(wm + 8 + gr) * LDW + kw + gcw + 4];
            #pragma unroll
            for (int ni = 0; ni < 8; ++ni) {
                uint32_t b0 = Btw[(ni * 8 + gr) * LDW + kw + gcw];
                uint32_t b1 = Btw[(ni * 8 + gr) * LDW + kw + gcw + 4];
                MMA16816(acc[ni][0], acc[ni][1], acc[ni][2], acc[ni][3],
                         a0, a1, a2, a3, b0, b1);
            }
        }

        size_t lb = ((hb * NCHUNK) + chunk) * (HEADDIM * DSTATE);
        int p0 = wm + gr, p1 = p0 + 8;
        #pragma unroll
        for (int ni = 0; ni < 8; ++ni) {
            int n0 = ni * 8 + 2 * gcw;
            *(float2*)&g_L[lb + (size_t)p0 * DSTATE + n0] = make_float2(acc[ni][0], acc[ni][1]);
            *(float2*)&g_L[lb + (size_t)p1 * DSTATE + n0] = make_float2(acc[ni][2], acc[ni][3]);
        }
    }
}

// ---------------- SSD pass B: sequential chunk-state combine -----------------
__global__ __launch_bounds__(64)
void ssd_combine_kernel()
{
    int blk = blockIdx.x;
    int h   = blk & 15;
    int b   = (blk >> 4) & 7;
    int dir = blk >> 7;
    int p   = threadIdx.x;

    const size_t hb = (size_t)(dir * BATCH + b) * NHEADS + h;

    float H[64];
    #pragma unroll
    for (int n = 0; n < 64; ++n) H[n] = 0.0f;

    for (int c = 0; c < NCHUNK; ++c) {
        size_t off = ((hb * NCHUNK) + c) * (HEADDIM * DSTATE) + (size_t)p * DSTATE;
        #pragma unroll
        for (int q = 0; q < 16; ++q)
            *(float4*)&g_Hi[off + q * 4] = make_float4(H[q*4], H[q*4+1], H[q*4+2], H[q*4+3]);
        if (c < NCHUNK - 1) {
            float P = g_cum[hb * SEQLEN + c * CHUNK + CHUNK - 1];
            #pragma unroll
            for (int q = 0; q < 16; ++q) {
                float4 L = *(const float4*)&g_L[off + q * 4];
                H[q*4+0] = fmaf(H[q*4+0], P, L.x);
                H[q*4+1] = fmaf(H[q*4+1], P, L.y);
                H[q*4+2] = fmaf(H[q*4+2], P, L.z);
                H[q*4+3] = fmaf(H[q*4+3], P, L.w);
            }
        }
    }
}

// ---------------- SSD pass C: fixup (MMA, fp32 y += ) ------------------------
__global__ __launch_bounds__(128)
void ssd_fixup_mma_kernel()
{
    __shared__ uint32_t Ash[64 * LDW];
    __shared__ uint32_t Bsh[64 * LDW];

    int idx  = blockIdx.x;
    int chunk = (idx % (NCHUNK - 1)) + 1;
    idx /= (NCHUNK - 1);
    int h   = idx & 15;
    int b   = (idx >> 4) & 7;
    int dir = idx >> 7;

    const __half* xch = dir ? g_xc1h : g_xc0h;
    float* yout = dir ? g_y1 : g_y0;
    const size_t hb = (size_t)(dir * BATCH + b) * NHEADS + h;
    const int t0 = chunk * CHUNK;
    const int tid = threadIdx.x;
    const int w    = tid >> 5;
    const int lane = tid & 31;
    const int gr   = lane >> 2;
    const int gcw  = lane & 3;
    const int wm   = w * 16;

    #pragma unroll
    for (int i = 0; i < 8; ++i) {
        int id = tid + i * 128;
        int row = id >> 4;
        int f4  = id & 15;
        uint2 v = *(const uint2*)&xch[(size_t)(b * SEQLEN + t0 + row) * CONVDIM
                                      + DINNER + DSTATE + f4 * 4];
        Ash[row * LDW + f4 * 2 + 0] = v.x;
        Ash[row * LDW + f4 * 2 + 1] = v.y;
    }
    {
        size_t hbase = ((hb * NCHUNK) + chunk) * (HEADDIM * DSTATE);
        #pragma unroll
        for (int i = 0; i < 8; ++i) {
            int id = tid + i * 128;
            int row = id >> 4;
            int f4  = id & 15;
            float4 v = *(const float4*)&g_Hi[hbase + (size_t)row * DSTATE + f4 * 4];
            Bsh[row * LDW + f4 * 2 + 0] = pack2h(v.x, v.y);
            Bsh[row * LDW + f4 * 2 + 1] = pack2h(v.z, v.w);
        }
    }
    __syncthreads();

    float acc[8][4];
    #pragma unroll
    for (int j = 0; j < 8; ++j)
        #pragma unroll
        for (int r = 0; r < 4; ++r) acc[j][r] = 0.0f;

    #pragma unroll
    for (int kk = 0; kk < 4; ++kk) {
        const int kw = kk * 8;
        uint32_t a0 = Ash[(wm + gr) * LDW + kw + gcw];
        uint32_t a1 = Ash[(wm + 8 + gr) * LDW + kw + gcw];
        uint32_t a2 = Ash[(wm + gr) * LDW + kw + gcw + 4];
        uint32_t a3 = Ash[(wm + 8 + gr) * LDW + kw + gcw + 4];
        #pragma unroll
        for (int ni = 0; ni < 8; ++ni) {
            uint32_t b0 = Bsh[(ni * 8 + gr) * LDW + kw + gcw];
            uint32_t b1 = Bsh[(ni * 8 + gr) * LDW + kw + gcw + 4];
            MMA16816(acc[ni][0], acc[ni][1], acc[ni][2], acc[ni][3],
                     a0, a1, a2, a3, b0, b1);
        }
    }

    int t_r0 = wm + gr, t_r1 = t_r0 + 8;
    float cum0 = g_cum[hb * SEQLEN + t0 + t_r0];
    float cum1 = g_cum[hb * SEQLEN + t0 + t_r1];
    size_t yb0 = (size_t)(b * SEQLEN + t0 + t_r0) * DINNER + h * HEADDIM;
    size_t yb1 = (size_t)(b * SEQLEN + t0 + t_r1) * DINNER + h * HEADDIM;
    #pragma unroll
    for (int ni = 0; ni < 8; ++ni) {
        int p0 = ni * 8 + 2 * gcw;
        yout[yb0 + p0]     += cum0 * acc[ni][0];
        yout[yb0 + p0 + 1] += cum0 * acc[ni][1];
        yout[yb1 + p0]     += cum1 * acc[ni][2];
        yout[yb1 + p0 + 1] += cum1 * acc[ni][3];
    }
}

// ---------------- gate + RMS + combine (fp32 y, fp16 z, fp16 G out) ----------
__global__ __launch_bounds__(256)
void gate_rms_combine_kernel(const float* __restrict__ norm_w)
{
    __shared__ float sdata[256];
    int bt = blockIdx.x;
    int b = bt / SEQLEN;
    int t = bt % SEQLEN;
    int tid = threadIdx.x;

    float gf[4], gb[4];
    float ssf = 0.0f, ssb = 0.0f;
    size_t zf = (size_t)bt * DINPROJ;
    size_t zb = (size_t)(b * SEQLEN + (SEQLEN - 1 - t)) * DINPROJ;
    #pragma unroll
    for (int i = 0; i < 4; ++i) {
        int j = tid + i * 256;
        float yv = g_y0[(size_t)bt * DINNER + j];
        float zv = __half2float(g_zxh[zf + j]);
        gf[i] = yv * siluf(zv);
        ssf = fmaf(gf[i], gf[i], ssf);

        float yv2 = g_y1[(size_t)bt * DINNER + j];
        float zv2 = __half2float(g_zxh[zb + j]);
        gb[i] = yv2 * siluf(zv2);
        ssb = fmaf(gb[i], gb[i], ssb);
    }
    float sumf = blockReduceSum(ssf, sdata);
    float sumb = blockReduceSum(ssb, sdata);
    float rf = rsqrtf(sumf / DINNER + 1e-5f);
    float rb = rsqrtf(sumb / DINNER + 1e-5f);

    #pragma unroll
    for (int i = 0; i < 4; ++i) {
        int j = tid + i * 256;
        float v = (gf[i] * rf + BETA * gb[i] * rb) * norm_w[j];
        g_Gh[(size_t)bt * DINNER + j] = __float2half_rn(v);
    }
}

// ---------------- LN1 ---------------------------------------------------------
__global__ __launch_bounds__(256)
void ln1_kernel(const float* __restrict__ emb,
                const float* __restrict__ w, const float* __restrict__ bln)
{
    __shared__ float sdata[256];
    int bt = blockIdx.x;
    int tid = threadIdx.x;
    size_t base = (size_t)bt * DMODEL;

    float v[2], s = 0.0f, sq = 0.0f;
    #pragma unroll
    for (int i = 0; i < 2; ++i) {
        int j = tid + i * 256;
        v[i] = g_O[base + j] + emb[base + j];
        s += v[i];
        sq = fmaf(v[i], v[i], sq);
    }
    float sum = blockReduceSum(s, sdata);
    float sumsq = blockReduceSum(sq, sdata);
    float mu = sum / DMODEL;
    float var = sumsq / DMODEL - mu * mu;
    float rs = rsqrtf(var + 1e-12f);
    #pragma unroll
    for (int i = 0; i < 2; ++i) {
        int j = tid + i * 256;
        float o = (v[i] - mu) * rs * w[j] + bln[j];
        g_Xln[base + j] = o;
        g_Xh [base + j] = __float2half_rn(o);
    }
}

// ---------------- LN2 ---------------------------------------------------------
__global__ __launch_bounds__(256)
void ln2_kernel(float* __restrict__ out,
                const float* __restrict__ w, const float* __restrict__ bln)
{
    __shared__ float sdata[256];
    int bt = blockIdx.x;
    int tid = threadIdx.x;
    size_t base = (size_t)bt * DMODEL;

    float v[2], s = 0.0f, sq = 0.0f;
    #pragma unroll
    for (int i = 0; i < 2; ++i) {
        int j = tid + i * 256;
        v[i] = g_H2[base + j] + g_Xln[base + j];
        s += v[i];
        sq = fmaf(v[i], v[i], sq);
    }
    float sum = blockReduceSum(s, sdata);
    float sumsq = blockReduceSum(sq, sdata);
    float mu = sum / DMODEL;
    float var = sumsq / DMODEL - mu * mu;
    float rs = rsqrtf(var + 1e-12f);
    #pragma unroll
    for (int i = 0; i < 2; ++i) {
        int j = tid + i * 256;
        out[base + j] = (v[i] - mu) * rs * w[j] + bln[j];
    }
}

// ---------------- launch -----------------------------------------------------
extern "C" void kernel_launch(void* const* d_in, const int* in_sizes, int n_in,
                              void* d_out, int out_size)
{
    const float* item_emb   = (const float*)d_in[0];
    const float* in_proj_w  = (const float*)d_in[3];
    const float* conv_w     = (const float*)d_in[4];
    const float* conv_b     = (const float*)d_in[5];
    const float* dt_bias    = (const float*)d_in[6];
    const float* A_log      = (const float*)d_in[7];
    const float* Dp         = (const float*)d_in[8];
    const float* norm_w     = (const float*)d_in[9];
    const float* out_proj_w = (const float*)d_in[10];
    const float* ln_w       = (const float*)d_in[11];
    const float* ln_b       = (const float*)d_in[12];
    const float* ffn_w1     = (const float*)d_in[13];
    const float* ffn_b1     = (const float*)d_in[14];
    const float* ffn_w2     = (const float*)d_in[15];
    const float* ffn_b2     = (const float*)d_in[16];
    const float* ffn_ln_w   = (const float*)d_in[17];
    const float* ffn_ln_b   = (const float*)d_in[18];
    float* out = (float*)d_out;

    float *p_O, *p_H2;
    __half *p_zxh, *p_embh, *p_Gh, *p_Xh, *p_H1h, *p_winh, *p_wouth, *p_w1h, *p_w2h;
    cudaGetSymbolAddress((void**)&p_zxh,  g_zxh);
    cudaGetSymbolAddress((void**)&p_O,    g_O);
    cudaGetSymbolAddress((void**)&p_H2,   g_H2);
    cudaGetSymbolAddress((void**)&p_embh, g_emb_h);
    cudaGetSymbolAddress((void**)&p_Gh,   g_Gh);
    cudaGetSymbolAddress((void**)&p_Xh,   g_Xh);
    cudaGetSymbolAddress((void**)&p_H1h,  g_H1h);
    cudaGetSymbolAddress((void**)&p_winh, g_win_h);
    cudaGetSymbolAddress((void**)&p_wouth,g_wout_h);
    cudaGetSymbolAddress((void**)&p_w1h,  g_w1_h);
    cudaGetSymbolAddress((void**)&p_w2h,  g_w2_h);

    cudaFuncSetAttribute(h16gemm<0,0>, cudaFuncAttributeMaxDynamicSharedMemorySize, GEMM_SMEM);
    cudaFuncSetAttribute(h16gemm<1,0>, cudaFuncAttributeMaxDynamicSharedMemorySize, GEMM_SMEM);
    cudaFuncSetAttribute(h16gemm256<0,1>, cudaFuncAttributeMaxDynamicSharedMemorySize, GEMM256_SMEM);
    cudaFuncSetAttribute(h16gemm256<2,1>, cudaFuncAttributeMaxDynamicSharedMemorySize, GEMM256_SMEM);

    // 0) all fp16 conversions in ONE launch
    cvt_all_kernel<<<(Q_TOT + 255) / 256, 256>>>(item_emb, in_proj_w, out_proj_w,
                                                 ffn_w1, ffn_w2);

    // 1) in_proj (8192 x 2192 x 512) -> fp16, 128x256 tiles
    {
        dim3 grid(DINPROJ_PAD / 256, NTOK / 128);
        h16gemm256<0,1><<<grid, 256, GEMM256_SMEM>>>(p_embh, p_winh, nullptr, p_zxh, NTOK, DINPROJ, DMODEL);
    }

    // 2) conv + silu -> fp16
    {
        int total = 2 * NTOK * (CONVDIM / 4);
        conv_silu_kernel<<<(total + 255) / 256, 256>>>(conv_w, conv_b);
    }

    // 3) dt softplus + log-decay
    {
        int total = NTOK * NHEADS;
        dt_kernel<<<(total + 255) / 256, 256>>>(dt_bias, A_log);
    }

    // 4) SSD: chunk GEMMs, combine, fixup
    ssd_chunk_mma_kernel<<<2*BATCH*NHEADS*NCHUNK, 128>>>(Dp);
    ssd_combine_kernel<<<256, 64>>>();
    ssd_fixup_mma_kernel<<<2*BATCH*NHEADS*(NCHUNK-1), 128>>>();

    // 5) gate + RMS + combine -> fp16 G
    gate_rms_combine_kernel<<<NTOK, 256>>>(norm_w);

    // 6) out_proj (8192 x 512 x 1024), 128x128 tiles
    {
        dim3 grid(DMODEL / 128, NTOK / 128);
        h16gemm<0,0><<<grid, 256, GEMM_SMEM>>>(p_Gh, p_wouth, nullptr, p_O, NTOK, DMODEL, DINNER);
    }

    // 7) LN1
    ln1_kernel<<<NTOK, 256>>>(item_emb, ln_w, ln_b);

    // 8) FFN1 (8192 x 2048 x 512), 128x256 tiles
    {
        dim3 grid(DFFN / 256, NTOK / 128);
        h16gemm256<2,1><<<grid, 256, GEMM256_SMEM>>>(p_Xh, p_w1h, ffn_b1, p_H1h, NTOK, DFFN, DMODEL);
    }

    // 9) FFN2 (8192 x 512 x 2048), 128x128 tiles
    {
        dim3 grid(DMODEL / 128, NTOK / 128);
        h16gemm<1,0><<<grid, 256, GEMM_SMEM>>>(p_H1h, p_w2h, ffn_b2, p_H2, NTOK, DMODEL, DFFN);
    }

    // 10) final LN
    ln2_kernel<<<NTOK, 256>>>(out, ffn_ln_w, ffn_ln_b);
}

// round 15
// speedup vs baseline: 1.0811x; 1.0811x over previous
#include <cuda_runtime.h>
#include <cuda_fp16.h>
#include <math.h>
#include <stdint.h>

#define BATCH   8
#define SEQLEN  1024
#define NTOK    (BATCH*SEQLEN)     // 8192
#define DMODEL  512
#define DSTATE  64
#define DINNER  1024
#define NHEADS  16
#define HEADDIM 64
#define DINPROJ 2192
#define DINPROJ_PAD 2304
#define CONVDIM 1152
#define DFFN    2048
#define BETA    0.5f
#define CHUNK   64
#define NCHUNK  16

// ---------------- scratch ----------------------------------------------------
__device__ __half g_zxh[NTOK*DINPROJ];
__device__ __half g_xc0h[NTOK*CONVDIM];
__device__ __half g_xc1h[NTOK*CONVDIM];
__device__ float  g_dt [NTOK*NHEADS];
__device__ float  g_ldA[NTOK*NHEADS];
__device__ float  g_y0 [NTOK*DINNER];
__device__ float  g_y1 [NTOK*DINNER];
__device__ float  g_O  [NTOK*DMODEL];
__device__ float  g_Xln[NTOK*DMODEL];
__device__ float  g_H2 [NTOK*DMODEL];
__device__ float  g_cum[2*BATCH*NHEADS*SEQLEN];
__device__ float  g_L  [2*BATCH*NHEADS*NCHUNK*HEADDIM*DSTATE];
__device__ float  g_Hi [2*BATCH*NHEADS*NCHUNK*HEADDIM*DSTATE];
// fp16 operands
__device__ __half g_emb_h[NTOK*DMODEL];
__device__ __half g_Gh   [NTOK*DINNER];
__device__ __half g_Xh   [NTOK*DMODEL];
__device__ __half g_H1h  [NTOK*DFFN];
__device__ __half g_win_h [DINPROJ_PAD*DMODEL];
__device__ __half g_wout_h[DMODEL*DINNER];
__device__ __half g_w1_h  [DFFN*DMODEL];
__device__ __half g_w2_h  [DMODEL*DFFN];

// ---------------- helpers ----------------------------------------------------
__device__ __forceinline__ float siluf(float v) {
    return v * __frcp_rn(1.0f + __expf(-v));
}
__device__ __forceinline__ float geluf(float v) { return 0.5f * v * (1.0f + erff(v * 0.70710678118654752f)); }
__device__ __forceinline__ float softplusf(float x) { return fmaxf(x, 0.0f) + log1pf(expf(-fabsf(x))); }

__device__ __forceinline__ void cpasync16(uint32_t saddr, const void* gptr) {
    asm volatile("cp.async.cg.shared.global [%0], [%1], 16;\n" :: "r"(saddr), "l"(gptr));
}
__device__ __forceinline__ void cp_commit() { asm volatile("cp.async.commit_group;\n"); }
__device__ __forceinline__ void cp_wait0()  { asm volatile("cp.async.wait_group 0;\n"); }
__device__ __forceinline__ void cp_wait1()  { asm volatile("cp.async.wait_group 1;\n"); }
__device__ __forceinline__ void cp_wait2()  { asm volatile("cp.async.wait_group 2;\n"); }

__device__ __forceinline__ void ldsm_x4(uint32_t& r0, uint32_t& r1, uint32_t& r2, uint32_t& r3,
                                        uint32_t saddr) {
    asm volatile("ldmatrix.sync.aligned.m8n8.x4.shared.b16 {%0,%1,%2,%3}, [%4];"
        : "=r"(r0), "=r"(r1), "=r"(r2), "=r"(r3) : "r"(saddr));
}

#define MMA16816(d0,d1,d2,d3,a0,a1,a2,a3,b0,b1) \
    asm volatile( \
        "mma.sync.aligned.m16n8k16.row.col.f32.f16.f16.f32 " \
        "{%0,%1,%2,%3}, {%4,%5,%6,%7}, {%8,%9}, {%0,%1,%2,%3};" \
        : "+f"(d0), "+f"(d1), "+f"(d2), "+f"(d3) \
        : "r"(a0), "r"(a1), "r"(a2), "r"(a3), "r"(b0), "r"(b1))

__device__ __forceinline__ float blockReduceSum(float v, float* sdata) {
    int tid = threadIdx.x;
    sdata[tid] = v; __syncthreads();
    for (int s = blockDim.x >> 1; s > 0; s >>= 1) {
        if (tid < s) sdata[tid] += sdata[tid + s];
        __syncthreads();
    }
    float r = sdata[0]; __syncthreads();
    return r;
}
__device__ __forceinline__ uint32_t pack2h(float x, float y) {
    __half2 h = __float22half2_rn(make_float2(x, y));
    return *(uint32_t*)&h;
}

// ---------------- fused fp32 -> fp16 converter (one launch) ------------------
#define Q_EMB  (NTOK*DMODEL/4)
#define Q_WIN  (DINPROJ_PAD*DMODEL/4)
#define Q_WOUT (DMODEL*DINNER/4)
#define Q_W1   (DFFN*DMODEL/4)
#define Q_W2   (DMODEL*DFFN/4)
#define Q_TOT  (Q_EMB+Q_WIN+Q_WOUT+Q_W1+Q_W2)

__global__ void cvt_all_kernel(const float* __restrict__ emb,
                               const float* __restrict__ win,
                               const float* __restrict__ wout,
                               const float* __restrict__ w1,
                               const float* __restrict__ w2)
{
    int q = blockIdx.x * blockDim.x + threadIdx.x;
    if (q >= Q_TOT) return;
    const float* src;
    __half* dst;
    int idx;
    if (q < Q_EMB)                       { src = emb;  dst = g_emb_h;  idx = q; }
    else if (q < Q_EMB+Q_WIN)            { src = win;  dst = g_win_h;  idx = q - Q_EMB;
        int row = (idx * 4) / DMODEL;
        if (row >= DINPROJ) {
            __half2* d = (__half2*)&dst[idx * 4];
            d[0] = __half2(__float2half(0.f), __float2half(0.f));
            d[1] = __half2(__float2half(0.f), __float2half(0.f));
            return;
        }
    }
    else if (q < Q_EMB+Q_WIN+Q_WOUT)     { src = wout; dst = g_wout_h; idx = q - (Q_EMB+Q_WIN); }
    else if (q < Q_EMB+Q_WIN+Q_WOUT+Q_W1){ src = w1;   dst = g_w1_h;   idx = q - (Q_EMB+Q_WIN+Q_WOUT); }
    else                                 { src = w2;   dst = g_w2_h;   idx = q - (Q_EMB+Q_WIN+Q_WOUT+Q_W1); }

    float4 v = *(const float4*)&src[idx * 4];
    __half2* d = (__half2*)&dst[idx * 4];
    d[0] = __float22half2_rn(make_float2(v.x, v.y));
    d[1] = __float22half2_rn(make_float2(v.z, v.w));
}

// ---------------- FP16 GEMM 128x128 (cp.async 4-stage) -----------------------
#define LDH 20
#define TILE_W (128 * LDH)
#define GEMM_SMEM (8 * TILE_W * 4)

template<int EPI, int OUTH>
__global__ __launch_bounds__(256, 2)
void h16gemm(const __half* __restrict__ A, const __half* __restrict__ B,
             const float* __restrict__ bias, void* __restrict__ Cv,
             int M, int N, int K)
{
    extern __shared__ uint32_t smemu[];
    uint32_t* AsB = smemu;
    uint32_t* BsB = smemu + 4 * TILE_W;

    const int tid = threadIdx.x;
    const int m0 = blockIdx.y * 128;
    const int n0 = blockIdx.x * 128;

    const int w    = tid >> 5;
    const int lane = tid & 31;
    const int wm   = (w >> 2) * 64;
    const int wn   = (w & 3) * 32;
    const int gr   = lane >> 2;
    const int gcw  = lane & 3;

    const int row0 = tid >> 2;
    const int c0   = tid & 3;

    uint32_t asb = (uint32_t)__cvta_generic_to_shared(AsB);
    uint32_t bsb = (uint32_t)__cvta_generic_to_shared(BsB);
    const uint32_t stg = TILE_W * 4;

    const uint32_t a_lane = (uint32_t)(((lane & 7) + ((lane >> 3) & 1) * 8) * 80
                                       + (lane >> 4) * 16);
    const uint32_t b_lane = (uint32_t)((lane & 15) * 80 + (lane >> 4) * 16);

    float acc[4][4][4];
    #pragma unroll
    for (int i = 0; i < 4; ++i)
        #pragma unroll
        for (int j = 0; j < 4; ++j)
            #pragma unroll
            for (int r = 0; r < 4; ++r) acc[i][j][r] = 0.0f;

    const int KT = K / 32;

    #pragma unroll
    for (int t = 0; t < 3; ++t) {
        if (t < KT) {
            size_t koff = (size_t)t * 32 + c0 * 8;
            #pragma unroll
            for (int i = 0; i < 2; ++i) {
                int row = row0 + i * 64;
                uint32_t doff = (uint32_t)t * stg + (uint32_t)(row * 80 + c0 * 16);
                cpasync16(asb + doff, A + (size_t)(m0 + row) * K + koff);
                cpasync16(bsb + doff, B + (size_t)(n0 + row) * K + koff);
            }
            cp_commit();
        }
    }

    for (int kt = 0; kt < KT; ++kt) {
        int rem = KT - 1 - kt;
        if (rem >= 2)      cp_wait2();
        else if (rem == 1) cp_wait1();
        else               cp_wait0();
        __syncthreads();

        if (kt + 3 < KT) {
            int nb = (kt + 3) & 3;
            size_t koff = (size_t)(kt + 3) * 32 + c0 * 8;
            #pragma unroll
            for (int i = 0; i < 2; ++i) {
                int row = row0 + i * 64;
                uint32_t doff = (uint32_t)nb * stg + (uint32_t)(row * 80 + c0 * 16);
                cpasync16(asb + doff, A + (size_t)(m0 + row) * K + koff);
                cpasync16(bsb + doff, B + (size_t)(n0 + row) * K + koff);
            }
            cp_commit();
        }

        const int cur = kt & 3;
        const uint32_t as_st = asb + (uint32_t)cur * stg;
        const uint32_t bs_st = bsb + (uint32_t)cur * stg;
        #pragma unroll
        for (int kk = 0; kk < 2; ++kk) {
            const uint32_t kb = (uint32_t)(kk * 32);
            uint32_t af[4][4];
            #pragma unroll
            for (int mi = 0; mi < 4; ++mi) {
                uint32_t sa = as_st + (uint32_t)((wm + mi * 16) * 80) + kb + a_lane;
                ldsm_x4(af[mi][0], af[mi][1], af[mi][2], af[mi][3], sa);
            }
            uint32_t bf[4][2];
            #pragma unroll
            for (int np = 0; np < 2; ++np) {
                uint32_t sb = bs_st + (uint32_t)((wn + np * 16) * 80) + kb + b_lane;
                ldsm_x4(bf[np*2][0], bf[np*2+1][0], bf[np*2][1], bf[np*2+1][1], sb);
            }
            #pragma unroll
            for (int mi = 0; mi < 4; ++mi)
                #pragma unroll
                for (int ni = 0; ni < 4; ++ni)
                    MMA16816(acc[mi][ni][0], acc[mi][ni][1], acc[mi][ni][2], acc[mi][ni][3],
                             af[mi][0], af[mi][1], af[mi][2], af[mi][3],
                             bf[ni][0], bf[ni][1]);
        }
    }

    float* Cf = (float*)Cv;
    __half* Ch = (__half*)Cv;
    #pragma unroll
    for (int mi = 0; mi < 4; ++mi) {
        int r = m0 + wm + mi * 16 + gr;
        #pragma unroll
        for (int ni = 0; ni < 4; ++ni) {
            int cb = n0 + wn + ni * 8 + 2 * gcw;
            #pragma unroll
            for (int half = 0; half < 2; ++half) {
                int rr = r + half * 8;
                float v0 = acc[mi][ni][half * 2 + 0];
                float v1 = acc[mi][ni][half * 2 + 1];
                if (cb < N) {
                    if (EPI >= 1) v0 += bias[cb];
                    if (EPI == 2) v0 = geluf(v0);
                    if (OUTH) Ch[(size_t)rr * N + cb] = __float2half_rn(v0);
                    else      Cf[(size_t)rr * N + cb] = v0;
                }
                if (cb + 1 < N) {
                    if (EPI >= 1) v1 += bias[cb + 1];
                    if (EPI == 2) v1 = geluf(v1);
                    if (OUTH) Ch[(size_t)rr * N + cb + 1] = __float2half_rn(v1);
                    else      Cf[(size_t)rr * N + cb + 1] = v1;
                }
            }
        }
    }
}

// ---------------- conv + silu + dt (fused, one launch) -----------------------
#define CONV_BLOCKS ((2 * NTOK * (CONVDIM/4) + 255) / 256)   // 2304
#define DT_BLOCKS   ((NTOK * NHEADS + 255) / 256)            // 512

__global__ void conv_dt_kernel(const float* __restrict__ conv_w,
                               const float* __restrict__ conv_b,
                               const float* __restrict__ dt_bias,
                               const float* __restrict__ A_log)
{
    if (blockIdx.x >= CONV_BLOCKS) {
        // dt part
        int e = (blockIdx.x - CONV_BLOCKS) * blockDim.x + threadIdx.x;
        if (e >= NTOK * NHEADS) return;
        int bt = e / NHEADS;
        int h  = e % NHEADS;
        float x = __half2float(g_zxh[(size_t)bt * DINPROJ + (DINNER + CONVDIM) + h]) + dt_bias[h];
        float dtv = softplusf(x);
        g_dt[e]  = dtv;
        g_ldA[e] = dtv * (-expf(A_log[h]));
        return;
    }

    int e = blockIdx.x * blockDim.x + threadIdx.x;
    const int C4 = CONVDIM / 4;
    const int total = 2 * NTOK * C4;
    if (e >= total) return;
    int dir = e / (NTOK * C4);
    int rem = e - dir * (NTOK * C4);
    int bt = rem / C4;
    int c4 = rem % C4;
    int b = bt / SEQLEN;
    int t = bt % SEQLEN;
    int c = c4 * 4;

    float4 w0 = *(const float4*)&conv_w[(c + 0) * 4];
    float4 w1 = *(const float4*)&conv_w[(c + 1) * 4];
    float4 w2 = *(const float4*)&conv_w[(c + 2) * 4];
    float4 w3 = *(const float4*)&conv_w[(c + 3) * 4];
    float4 acc = *(const float4*)&conv_b[c];

    float wt0[4] = {w0.x, w0.y, w0.z, w0.w};
    float wt1[4] = {w1.x, w1.y, w1.z, w1.w};
    float wt2[4] = {w2.x, w2.y, w2.z, w2.w};
    float wt3[4] = {w3.x, w3.y, w3.z, w3.w};

    #pragma unroll
    for (int k = 0; k < 4; ++k) {
        int tp = t - 3 + k;
        if (tp >= 0) {
            int s = dir ? (SEQLEN - 1 - tp) : tp;
            uint2 raw = *(const uint2*)&g_zxh[(size_t)(b * SEQLEN + s) * DINPROJ + DINNER + c];
            float2 v01 = __half22float2(*(__half2*)&raw.x);
            float2 v23 = __half22float2(*(__half2*)&raw.y);
            acc.x = fmaf(wt0[k], v01.x, acc.x);
            acc.y = fmaf(wt1[k], v01.y, acc.y);
            acc.z = fmaf(wt2[k], v23.x, acc.z);
            acc.w = fmaf(wt3[k], v23.y, acc.w);
        }
    }
    uint2 o;
    o.x = pack2h(siluf(acc.x), siluf(acc.y));
    o.y = pack2h(siluf(acc.z), siluf(acc.w));
    __half* out = dir ? g_xc1h : g_xc0h;
    *(uint2*)&out[(size_t)bt * CONVDIM + c] = o;
}

// ---------------- SSD pass A: chunk GEMMs ------------------------------------
#define LDW 36

__global__ __launch_bounds__(128)
void ssd_chunk_mma_kernel(const float* __restrict__ Dp)
{
    __shared__ uint32_t Ck [64 * LDW];
    __shared__ uint32_t Bk [64 * LDW];
    __shared__ uint32_t Xt [64 * LDW];
    __shared__ uint32_t Btw[64 * LDW];
    __shared__ uint32_t Wsm[64 * LDW];
    __shared__ float sdt[64];
    __shared__ float slc[64];

    int blk   = blockIdx.x;
    int chunk = blk & 15;
    int h     = (blk >> 4) & 15;
    int b     = (blk >> 8) & 7;
    int dir   = blk >> 11;
    const int tid  = threadIdx.x;
    const int w    = tid >> 5;
    const int lane = tid & 31;
    const int gr   = lane >> 2;
    const int gcw  = lane & 3;
    const int wm   = w * 16;

    const __half* xch = dir ? g_xc1h : g_xc0h;
    float* yout = dir ? g_y1 : g_y0;
    const size_t hb = (size_t)(dir * BATCH + b) * NHEADS + h;
    const int t0 = chunk * CHUNK;

    if (tid < 64) {
        int t = t0 + tid;
        int s = dir ? (SEQLEN - 1 - t) : t;
        size_t de = (size_t)(b * SEQLEN + s) * NHEADS + h;
        sdt[tid] = g_dt[de];
        slc[tid] = g_ldA[de];
    }
    __syncthreads();
    #pragma unroll
    for (int off = 1; off < 64; off <<= 1) {
        float add = 0.0f;
        if (tid < 64 && tid >= off) add = slc[tid - off];
        __syncthreads();
        if (tid < 64) slc[tid] += add;
        __syncthreads();
    }
    if (tid < 64) g_cum[hb * SEQLEN + t0 + tid] = __expf(slc[tid]);
    __syncthreads();
    const float lcLast = slc[63];

    __half* XtH  = (__half*)Xt;
    __half* BtwH = (__half*)Btw;

    #pragma unroll
    for (int i = 0; i < 8; ++i) {
        int id = tid + i * 128;
        int row = id >> 4;
        int f4  = id & 15;
        size_t base = (size_t)(b * SEQLEN + t0 + row) * CONVDIM + DINNER;
        uint2 vb = *(const uint2*)&xch[base + f4 * 4];
        uint2 vc = *(const uint2*)&xch[base + DSTATE + f4 * 4];
        Bk[row * LDW + f4 * 2 + 0] = vb.x;
        Bk[row * LDW + f4 * 2 + 1] = vb.y;
        Ck[row * LDW + f4 * 2 + 0] = vc.x;
        Ck[row * LDW + f4 * 2 + 1] = vc.y;
    }
    #pragma unroll
    for (int i = 0; i < 8; ++i) {
        int id = tid + i * 128;
        int srow = id >> 4;
        int f4   = id & 15;
        size_t base = (size_t)(b * SEQLEN + t0 + srow) * CONVDIM;
        float w2f = sdt[srow] * __expf(lcLast - slc[srow]);
        __half2 w2h = __float2half2_rn(w2f);

        uint2 vx = *(const uint2*)&xch[base + h * HEADDIM + f4 * 4];
        __half2 x01 = *(__half2*)&vx.x;
        __half2 x23 = *(__half2*)&vx.y;
        XtH[(f4*4+0) * 72 + srow] = __low2half(x01);
        XtH[(f4*4+1) * 72 + srow] = __high2half(x01);
        XtH[(f4*4+2) * 72 + srow] = __low2half(x23);
        XtH[(f4*4+3) * 72 + srow] = __high2half(x23);

        uint2 vb = *(const uint2*)&xch[base + DINNER + f4 * 4];
        __half2 b01 = __hmul2(*(__half2*)&vb.x, w2h);
        __half2 b23 = __hmul2(*(__half2*)&vb.y, w2h);
        BtwH[(f4*4+0) * 72 + srow] = __low2half(b01);
        BtwH[(f4*4+1) * 72 + srow] = __high2half(b01);
        BtwH[(f4*4+2) * 72 + srow] = __low2half(b23);
        BtwH[(f4*4+3) * 72 + srow] = __high2half(b23);
    }
    __syncthreads();

    // GEMM 1: G = Ck @ Bk^T
    {
        float acc[8][4];
        #pragma unroll
        for (int j = 0; j < 8; ++j)
            #pragma unroll
            for (int r = 0; r < 4; ++r) acc[j][r] = 0.0f;

        #pragma unroll
        for (int kk = 0; kk < 4; ++kk) {
            const int kw = kk * 8;
            uint32_t a0 = Ck[(wm + gr) * LDW + kw + gcw];
            uint32_t a1 = Ck[(wm + 8 + gr) * LDW + kw + gcw];
            uint32_t a2 = Ck[(wm + gr) * LDW + kw + gcw + 4];
            uint32_t a3 = Ck[(wm + 8 + gr) * LDW + kw + gcw + 4];
            #pragma unroll
            for (int ni = 0; ni < 8; ++ni) {
                uint32_t b0 = Bk[(ni * 8 + gr) * LDW + kw + gcw];
                uint32_t b1 = Bk[(ni * 8 + gr) * LDW + kw + gcw + 4];
                MMA16816(acc[ni][0], acc[ni][1], acc[ni][2], acc[ni][3],
                         a0, a1, a2, a3, b0, b1);
            }
        }

        int t_r0 = wm + gr, t_r1 = wm + gr + 8;
        float lt0 = slc[t_r0], lt1 = slc[t_r1];
        #pragma unroll
        for (int ni = 0; ni < 8; ++ni) {
            int s0 = ni * 8 + 2 * gcw;
            int s1 = s0 + 1;
            float ls0 = slc[s0], ls1 = slc[s1];
            float d0 = sdt[s0],  d1 = sdt[s1];
            float w00 = (s0 <= t_r0) ? __expf(lt0 - ls0) * d0 * acc[ni][0] : 0.0f;
            float w01 = (s1 <= t_r0) ? __expf(lt0 - ls1) * d1 * acc[ni][1] : 0.0f;
            float w10 = (s0 <= t_r1) ? __expf(lt1 - ls0) * d0 * acc[ni][2] : 0.0f;
            float w11 = (s1 <= t_r1) ? __expf(lt1 - ls1) * d1 * acc[ni][3] : 0.0f;
            Wsm[t_r0 * LDW + ni * 4 + gcw] = pack2h(w00, w01);
            Wsm[t_r1 * LDW + ni * 4 + gcw] = pack2h(w10, w11);
        }
    }
    __syncthreads();

    // GEMM 2: Y = W @ X
    {
        float acc[8][4];
        #pragma unroll
        for (int j = 0; j < 8; ++j)
            #pragma unroll
            for (int r = 0; r < 4; ++r) acc[j][r] = 0.0f;

        #pragma unroll
        for (int kk = 0; kk < 4; ++kk) {
            const int kw = kk * 8;
            uint32_t a0 = Wsm[(wm + gr) * LDW + kw + gcw];
            uint32_t a1 = Wsm[(wm + 8 + gr) * LDW + kw + gcw];
            uint32_t a2 = Wsm[(wm + gr) * LDW + kw + gcw + 4];
            uint32_t a3 = Wsm[(wm + 8 + gr) * LDW + kw + gcw + 4];
            #pragma unroll
            for (int ni = 0; ni < 8; ++ni) {
                uint32_t b0 = Xt[(ni * 8 + gr) * LDW + kw + gcw];
                uint32_t b1 = Xt[(ni * 8 + gr) * LDW + kw + gcw + 4];
                MMA16816(acc[ni][0], acc[ni][1], acc[ni][2], acc[ni][3],
                         a0, a1, a2, a3, b0, b1);
            }
        }

        float Dh = Dp[h];
        int t_r0 = wm + gr, t_r1 = t_r0 + 8;
        size_t yb0 = (size_t)(b * SEQLEN + t0 + t_r0) * DINNER + h * HEADDIM;
        size_t yb1 = (size_t)(b * SEQLEN + t0 + t_r1) * DINNER + h * HEADDIM;
        #pragma unroll
        for (int ni = 0; ni < 8; ++ni) {
            int p0 = ni * 8 + 2 * gcw;
            float x00 = __half2float(XtH[p0 * 72 + t_r0]);
            float x01 = __half2float(XtH[(p0+1) * 72 + t_r0]);
            float x10 = __half2float(XtH[p0 * 72 + t_r1]);
            float x11 = __half2float(XtH[(p0+1) * 72 + t_r1]);
            yout[yb0 + p0]     = acc[ni][0] + Dh * x00;
            yout[yb0 + p0 + 1] = acc[ni][1] + Dh * x01;
            yout[yb1 + p0]     = acc[ni][2] + Dh * x10;
            yout[yb1 + p0 + 1] = acc[ni][3] + Dh * x11;
        }
    }

    // GEMM 3: S[p][n] = Xt[p][s] @ Btw[n][s]^T
    {
        float acc[8][4];
        #pragma unroll
        for (int j = 0; j < 8; ++j)
            #pragma unroll
            for (int r = 0; r < 4; ++r) acc[j][r] = 0.0f;

        #pragma unroll
        for (int kk = 0; kk < 4; ++kk) {
            const int kw = kk * 8;
            uint32_t a0 = Xt[(wm + gr) * LDW + kw + gcw];
            uint32_t a1 = Xt[(wm + 8 + gr) * LDW + kw + gcw];
            uint32_t a2 = Xt[(wm + gr) * LDW + kw + gcw + 4];
            uint32_t a3 = Xt[(wm + 8 + gr) * LDW + kw + gcw + 4];
            #pragma unroll
            for (int ni = 0; ni < 8; ++ni) {
                uint32_t b0 = Btw[(ni * 8 + gr) * LDW + kw + gcw];
                uint32_t b1 = Btw[(ni * 8 + gr) * LDW + kw + gcw + 4];
                MMA16816(acc[ni][0], acc[ni][1], acc[ni][2], acc[ni][3],
                         a0, a1, a2, a3, b0, b1);
            }
        }

        size_t lb = ((hb * NCHUNK) + chunk) * (HEADDIM * DSTATE);
        int p0 = wm + gr, p1 = p0 + 8;
        #pragma unroll
        for (int ni = 0; ni < 8; ++ni) {
            int n0 = ni * 8 + 2 * gcw;
            *(float2*)&g_L[lb + (size_t)p0 * DSTATE + n0] = make_float2(acc[ni][0], acc[ni][1]);
            *(float2*)&g_L[lb + (size_t)p1 * DSTATE + n0] = make_float2(acc[ni][2], acc[ni][3]);
        }
    }
}

// ---------------- SSD pass B: sequential chunk-state combine -----------------
__global__ __launch_bounds__(64)
void ssd_combine_kernel()
{
    int blk = blockIdx.x;
    int h   = blk & 15;
    int b   = (blk >> 4) & 7;
    int dir = blk >> 7;
    int p   = threadIdx.x;

    const size_t hb = (size_t)(dir * BATCH + b) * NHEADS + h;

    float H[64];
    #pragma unroll
    for (int n = 0; n < 64; ++n) H[n] = 0.0f;

    for (int c = 0; c < NCHUNK; ++c) {
        size_t off = ((hb * NCHUNK) + c) * (HEADDIM * DSTATE) + (size_t)p * DSTATE;
        #pragma unroll
        for (int q = 0; q < 16; ++q)
            *(float4*)&g_Hi[off + q * 4] = make_float4(H[q*4], H[q*4+1], H[q*4+2], H[q*4+3]);
        if (c < NCHUNK - 1) {
            float P = g_cum[hb * SEQLEN + c * CHUNK + CHUNK - 1];
            #pragma unroll
            for (int q = 0; q < 16; ++q) {
                float4 L = *(const float4*)&g_L[off + q * 4];
                H[q*4+0] = fmaf(H[q*4+0], P, L.x);
                H[q*4+1] = fmaf(H[q*4+1], P, L.y);
                H[q*4+2] = fmaf(H[q*4+2], P, L.z);
                H[q*4+3] = fmaf(H[q*4+3], P, L.w);
            }
        }
    }
}

// ---------------- SSD pass C: fixup (MMA, fp32 y += ) ------------------------
__global__ __launch_bounds__(128)
void ssd_fixup_mma_kernel()
{
    __shared__ uint32_t Ash[64 * LDW];
    __shared__ uint32_t Bsh[64 * LDW];

    int idx  = blockIdx.x;
    int chunk = (idx % (NCHUNK - 1)) + 1;
    idx /= (NCHUNK - 1);
    int h   = idx & 15;
    int b   = (idx >> 4) & 7;
    int dir = idx >> 7;

    const __half* xch = dir ? g_xc1h : g_xc0h;
    float* yout = dir ? g_y1 : g_y0;
    const size_t hb = (size_t)(dir * BATCH + b) * NHEADS + h;
    const int t0 = chunk * CHUNK;
    const int tid = threadIdx.x;
    const int w    = tid >> 5;
    const int lane = tid & 31;
    const int gr   = lane >> 2;
    const int gcw  = lane & 3;
    const int wm   = w * 16;

    #pragma unroll
    for (int i = 0; i < 8; ++i) {
        int id = tid + i * 128;
        int row = id >> 4;
        int f4  = id & 15;
        uint2 v = *(const uint2*)&xch[(size_t)(b * SEQLEN + t0 + row) * CONVDIM
                                      + DINNER + DSTATE + f4 * 4];
        Ash[row * LDW + f4 * 2 + 0] = v.x;
        Ash[row * LDW + f4 * 2 + 1] = v.y;
    }
    {
        size_t hbase = ((hb * NCHUNK) + chunk) * (HEADDIM * DSTATE);
        #pragma unroll
        for (int i = 0; i < 8; ++i) {
            int id = tid + i * 128;
            int row = id >> 4;
            int f4  = id & 15;
            float4 v = *(const float4*)&g_Hi[hbase + (size_t)row * DSTATE + f4 * 4];
            Bsh[row * LDW + f4 * 2 + 0] = pack2h(v.x, v.y);
            Bsh[row * LDW + f4 * 2 + 1] = pack2h(v.z, v.w);
        }
    }
    __syncthreads();

    float acc[8][4];
    #pragma unroll
    for (int j = 0; j < 8; ++j)
        #pragma unroll
        for (int r = 0; r < 4; ++r) acc[j][r] = 0.0f;

    #pragma unroll
    for (int kk = 0; kk < 4; ++kk) {
        const int kw = kk * 8;
        uint32_t a0 = Ash[(wm + gr) * LDW + kw + gcw];
        uint32_t a1 = Ash[(wm + 8 + gr) * LDW + kw + gcw];
        uint32_t a2 = Ash[(wm + gr) * LDW + kw + gcw + 4];
        uint32_t a3 = Ash[(wm + 8 + gr) * LDW + kw + gcw + 4];
        #pragma unroll
        for (int ni = 0; ni < 8; ++ni) {
            uint32_t b0 = Bsh[(ni * 8 + gr) * LDW + kw + gcw];
            uint32_t b1 = Bsh[(ni * 8 + gr) * LDW + kw + gcw + 4];
            MMA16816(acc[ni][0], acc[ni][1], acc[ni][2], acc[ni][3],
                     a0, a1, a2, a3, b0, b1);
        }
    }

    int t_r0 = wm + gr, t_r1 = t_r0 + 8;
    float cum0 = g_cum[hb * SEQLEN + t0 + t_r0];
    float cum1 = g_cum[hb * SEQLEN + t0 + t_r1];
    size_t yb0 = (size_t)(b * SEQLEN + t0 + t_r0) * DINNER + h * HEADDIM;
    size_t yb1 = (size_t)(b * SEQLEN + t0 + t_r1) * DINNER + h * HEADDIM;
    #pragma unroll
    for (int ni = 0; ni < 8; ++ni) {
        int p0 = ni * 8 + 2 * gcw;
        yout[yb0 + p0]     += cum0 * acc[ni][0];
        yout[yb0 + p0 + 1] += cum0 * acc[ni][1];
        yout[yb1 + p0]     += cum1 * acc[ni][2];
        yout[yb1 + p0 + 1] += cum1 * acc[ni][3];
    }
}

// ---------------- gate + RMS + combine (fp32 y, fp16 z, fp16 G out) ----------
__global__ __launch_bounds__(256)
void gate_rms_combine_kernel(const float* __restrict__ norm_w)
{
    __shared__ float sdata[256];
    int bt = blockIdx.x;
    int b = bt / SEQLEN;
    int t = bt % SEQLEN;
    int tid = threadIdx.x;

    float gf[4], gb[4];
    float ssf = 0.0f, ssb = 0.0f;
    size_t zf = (size_t)bt * DINPROJ;
    size_t zb = (size_t)(b * SEQLEN + (SEQLEN - 1 - t)) * DINPROJ;
    #pragma unroll
    for (int i = 0; i < 4; ++i) {
        int j = tid + i * 256;
        float yv = g_y0[(size_t)bt * DINNER + j];
        float zv = __half2float(g_zxh[zf + j]);
        gf[i] = yv * siluf(zv);
        ssf = fmaf(gf[i], gf[i], ssf);

        float yv2 = g_y1[(size_t)bt * DINNER + j];
        float zv2 = __half2float(g_zxh[zb + j]);
        gb[i] = yv2 * siluf(zv2);
        ssb = fmaf(gb[i], gb[i], ssb);
    }
    float sumf = blockReduceSum(ssf, sdata);
    float sumb = blockReduceSum(ssb, sdata);
    float rf = rsqrtf(sumf / DINNER + 1e-5f);
    float rb = rsqrtf(sumb / DINNER + 1e-5f);

    #pragma unroll
    for (int i = 0; i < 4; ++i) {
        int j = tid + i * 256;
        float v = (gf[i] * rf + BETA * gb[i] * rb) * norm_w[j];
        g_Gh[(size_t)bt * DINNER + j] = __float2half_rn(v);
    }
}

// ---------------- LN1 ---------------------------------------------------------
__global__ __launch_bounds__(256)
void ln1_kernel(const float* __restrict__ emb,
                const float* __restrict__ w, const float* __restrict__ bln)
{
    __shared__ float sdata[256];
    int bt = blockIdx.x;
    int tid = threadIdx.x;
    size_t base = (size_t)bt * DMODEL;

    float v[2], s = 0.0f, sq = 0.0f;
    #pragma unroll
    for (int i = 0; i < 2; ++i) {
        int j = tid + i * 256;
        v[i] = g_O[base + j] + emb[base + j];
        s += v[i];
        sq = fmaf(v[i], v[i], sq);
    }
    float sum = blockReduceSum(s, sdata);
    float sumsq = blockReduceSum(sq, sdata);
    float mu = sum / DMODEL;
    float var = sumsq / DMODEL - mu * mu;
    float rs = rsqrtf(var + 1e-12f);
    #pragma unroll
    for (int i = 0; i < 2; ++i) {
        int j = tid + i * 256;
        float o = (v[i] - mu) * rs * w[j] + bln[j];
        g_Xln[base + j] = o;
        g_Xh [base + j] = __float2half_rn(o);
    }
}

// ---------------- LN2 ---------------------------------------------------------
__global__ __launch_bounds__(256)
void ln2_kernel(float* __restrict__ out,
                const float* __restrict__ w, const float* __restrict__ bln)
{
    __shared__ float sdata[256];
    int bt = blockIdx.x;
    int tid = threadIdx.x;
    size_t base = (size_t)bt * DMODEL;

    float v[2], s = 0.0f, sq = 0.0f;
    #pragma unroll
    for (int i = 0; i < 2; ++i) {
        int j = tid + i * 256;
        v[i] = g_H2[base + j] + g_Xln[base + j];
        s += v[i];
        sq = fmaf(v[i], v[i], sq);
    }
    float sum = blockReduceSum(s, sdata);
    float sumsq = blockReduceSum(sq, sdata);
    float mu = sum / DMODEL;
    float var = sumsq / DMODEL - mu * mu;
    float rs = rsqrtf(var + 1e-12f);
    #pragma unroll
    for (int i = 0; i < 2; ++i) {
        int j = tid + i * 256;
        out[base + j] = (v[i] - mu) * rs * w[j] + bln[j];
    }
}

// ---------------- launch -----------------------------------------------------
extern "C" void kernel_launch(void* const* d_in, const int* in_sizes, int n_in,
                              void* d_out, int out_size)
{
    const float* item_emb   = (const float*)d_in[0];
    const float* in_proj_w  = (const float*)d_in[3];
    const float* conv_w     = (const float*)d_in[4];
    const float* conv_b     = (const float*)d_in[5];
    const float* dt_bias    = (const float*)d_in[6];
    const float* A_log      = (const float*)d_in[7];
    const float* Dp         = (const float*)d_in[8];
    const float* norm_w     = (const float*)d_in[9];
    const float* out_proj_w = (const float*)d_in[10];
    const float* ln_w       = (const float*)d_in[11];
    const float* ln_b       = (const float*)d_in[12];
    const float* ffn_w1     = (const float*)d_in[13];
    const float* ffn_b1     = (const float*)d_in[14];
    const float* ffn_w2     = (const float*)d_in[15];
    const float* ffn_b2     = (const float*)d_in[16];
    const float* ffn_ln_w   = (const float*)d_in[17];
    const float* ffn_ln_b   = (const float*)d_in[18];
    float* out = (float*)d_out;

    float *p_O, *p_H2;
    __half *p_zxh, *p_embh, *p_Gh, *p_Xh, *p_H1h, *p_winh, *p_wouth, *p_w1h, *p_w2h;
    cudaGetSymbolAddress((void**)&p_zxh,  g_zxh);
    cudaGetSymbolAddress((void**)&p_O,    g_O);
    cudaGetSymbolAddress((void**)&p_H2,   g_H2);
    cudaGetSymbolAddress((void**)&p_embh, g_emb_h);
    cudaGetSymbolAddress((void**)&p_Gh,   g_Gh);
    cudaGetSymbolAddress((void**)&p_Xh,   g_Xh);
    cudaGetSymbolAddress((void**)&p_H1h,  g_H1h);
    cudaGetSymbolAddress((void**)&p_winh, g_win_h);
    cudaGetSymbolAddress((void**)&p_wouth,g_wout_h);
    cudaGetSymbolAddress((void**)&p_w1h,  g_w1_h);
    cudaGetSymbolAddress((void**)&p_w2h,  g_w2_h);

    cudaFuncSetAttribute(h16gemm<0,0>, cudaFuncAttributeMaxDynamicSharedMemorySize, GEMM_SMEM);
    cudaFuncSetAttribute(h16gemm<0,1>, cudaFuncAttributeMaxDynamicSharedMemorySize, GEMM_SMEM);
    cudaFuncSetAttribute(h16gemm<2,1>, cudaFuncAttributeMaxDynamicSharedMemorySize, GEMM_SMEM);
    cudaFuncSetAttribute(h16gemm<1,0>, cudaFuncAttributeMaxDynamicSharedMemorySize, GEMM_SMEM);

    // 0) all fp16 conversions in ONE launch
    cvt_all_kernel<<<(Q_TOT + 255) / 256, 256>>>(item_emb, in_proj_w, out_proj_w,
                                                 ffn_w1, ffn_w2);

    // 1) in_proj (8192 x 2192 x 512) -> fp16
    {
        dim3 grid(DINPROJ_PAD / 128, NTOK / 128);
        h16gemm<0,1><<<grid, 256, GEMM_SMEM>>>(p_embh, p_winh, nullptr, p_zxh, NTOK, DINPROJ, DMODEL);
    }

    // 2+3) conv + silu + dt (fused)
    conv_dt_kernel<<<CONV_BLOCKS + DT_BLOCKS, 256>>>(conv_w, conv_b, dt_bias, A_log);

    // 4) SSD: chunk GEMMs, combine, fixup
    ssd_chunk_mma_kernel<<<2*BATCH*NHEADS*NCHUNK, 128>>>(Dp);
    ssd_combine_kernel<<<256, 64>>>();
    ssd_fixup_mma_kernel<<<2*BATCH*NHEADS*(NCHUNK-1), 128>>>();

    // 5) gate + RMS + combine -> fp16 G
    gate_rms_combine_kernel<<<NTOK, 256>>>(norm_w);

    // 6) out_proj (8192 x 512 x 1024)
    {
        dim3 grid(DMODEL / 128, NTOK / 128);
        h16gemm<0,0><<<grid, 256, GEMM_SMEM>>>(p_Gh, p_wouth, nullptr, p_O, NTOK, DMODEL, DINNER);
    }

    // 7) LN1
    ln1_kernel<<<NTOK, 256>>>(item_emb, ln_w, ln_b);

    // 8) FFN1 (8192 x 2048 x 512)
    {
        dim3 grid(DFFN / 128, NTOK / 128);
        h16gemm<2,1><<<grid, 256, GEMM_SMEM>>>(p_Xh, p_w1h, ffn_b1, p_H1h, NTOK, DFFN, DMODEL);
    }

    // 9) FFN2 (8192 x 512 x 2048)
    {
        dim3 grid(DMODEL / 128, NTOK / 128);
        h16gemm<1,0><<<grid, 256, GEMM_SMEM>>>(p_H1h, p_w2h, ffn_b2, p_H2, NTOK, DMODEL, DFFN);
    }

    // 10) final LN
    ln2_kernel<<<NTOK, 256>>>(out, ffn_ln_w, ffn_ln_b);
}

// round 16
// speedup vs baseline: 1.1165x; 1.0327x over previous
#include <cuda_runtime.h>
#include <cuda_fp16.h>
#include <math.h>
#include <stdint.h>

#define BATCH   8
#define SEQLEN  1024
#define NTOK    (BATCH*SEQLEN)     // 8192
#define DMODEL  512
#define DSTATE  64
#define DINNER  1024
#define NHEADS  16
#define HEADDIM 64
#define DINPROJ 2192
#define DINPROJ_PAD 2304
#define CONVDIM 1152
#define DFFN    2048
#define BETA    0.5f
#define CHUNK   64
#define NCHUNK  16

// ---------------- scratch ----------------------------------------------------
__device__ __half g_zxh[NTOK*DINPROJ];
__device__ __half g_xc0h[NTOK*CONVDIM];
__device__ __half g_xc1h[NTOK*CONVDIM];
__device__ float  g_dt [NTOK*NHEADS];
__device__ float  g_ldA[NTOK*NHEADS];
__device__ float  g_y0 [NTOK*DINNER];
__device__ float  g_y1 [NTOK*DINNER];
__device__ float  g_O  [NTOK*DMODEL];
__device__ float  g_Xln[NTOK*DMODEL];
__device__ float  g_H2 [NTOK*DMODEL];
__device__ float  g_cum[2*BATCH*NHEADS*SEQLEN];
__device__ float  g_L  [2*BATCH*NHEADS*NCHUNK*HEADDIM*DSTATE];
__device__ float  g_Hi [2*BATCH*NHEADS*NCHUNK*HEADDIM*DSTATE];
// fp16 operands
__device__ __half g_emb_h[NTOK*DMODEL];
__device__ __half g_Gh   [NTOK*DINNER];
__device__ __half g_Xh   [NTOK*DMODEL];
__device__ __half g_H1h  [NTOK*DFFN];
__device__ __half g_win_h [DINPROJ_PAD*DMODEL];
__device__ __half g_wout_h[DMODEL*DINNER];
__device__ __half g_w1_h  [DFFN*DMODEL];
__device__ __half g_w2_h  [DMODEL*DFFN];

// ---------------- helpers ----------------------------------------------------
__device__ __forceinline__ float siluf(float v) {
    return v * __frcp_rn(1.0f + __expf(-v));
}
__device__ __forceinline__ float geluf(float v) { return 0.5f * v * (1.0f + erff(v * 0.70710678118654752f)); }
__device__ __forceinline__ float softplusf(float x) { return fmaxf(x, 0.0f) + log1pf(expf(-fabsf(x))); }

__device__ __forceinline__ void cpasync16(uint32_t saddr, const void* gptr) {
    asm volatile("cp.async.cg.shared.global [%0], [%1], 16;\n" :: "r"(saddr), "l"(gptr));
}
__device__ __forceinline__ void cp_commit() { asm volatile("cp.async.commit_group;\n"); }
__device__ __forceinline__ void cp_wait0()  { asm volatile("cp.async.wait_group 0;\n"); }
__device__ __forceinline__ void cp_wait1()  { asm volatile("cp.async.wait_group 1;\n"); }
__device__ __forceinline__ void cp_wait2()  { asm volatile("cp.async.wait_group 2;\n"); }

__device__ __forceinline__ void ldsm_x4(uint32_t& r0, uint32_t& r1, uint32_t& r2, uint32_t& r3,
                                        uint32_t saddr) {
    asm volatile("ldmatrix.sync.aligned.m8n8.x4.shared.b16 {%0,%1,%2,%3}, [%4];"
        : "=r"(r0), "=r"(r1), "=r"(r2), "=r"(r3) : "r"(saddr));
}

#define MMA16816(d0,d1,d2,d3,a0,a1,a2,a3,b0,b1) \
    asm volatile( \
        "mma.sync.aligned.m16n8k16.row.col.f32.f16.f16.f32 " \
        "{%0,%1,%2,%3}, {%4,%5,%6,%7}, {%8,%9}, {%0,%1,%2,%3};" \
        : "+f"(d0), "+f"(d1), "+f"(d2), "+f"(d3) \
        : "r"(a0), "r"(a1), "r"(a2), "r"(a3), "r"(b0), "r"(b1))

__device__ __forceinline__ float blockReduceSum(float v, float* sdata) {
    int tid = threadIdx.x;
    sdata[tid] = v; __syncthreads();
    for (int s = blockDim.x >> 1; s > 0; s >>= 1) {
        if (tid < s) sdata[tid] += sdata[tid + s];
        __syncthreads();
    }
    float r = sdata[0]; __syncthreads();
    return r;
}
__device__ __forceinline__ uint32_t pack2h(float x, float y) {
    __half2 h = __float22half2_rn(make_float2(x, y));
    return *(uint32_t*)&h;
}

// ---------------- fused fp32 -> fp16 converter (one launch) ------------------
#define Q_EMB  (NTOK*DMODEL/4)
#define Q_WIN  (DINPROJ_PAD*DMODEL/4)
#define Q_WOUT (DMODEL*DINNER/4)
#define Q_W1   (DFFN*DMODEL/4)
#define Q_W2   (DMODEL*DFFN/4)
#define Q_TOT  (Q_EMB+Q_WIN+Q_WOUT+Q_W1+Q_W2)

__global__ void cvt_all_kernel(const float* __restrict__ emb,
                               const float* __restrict__ win,
                               const float* __restrict__ wout,
                               const float* __restrict__ w1,
                               const float* __restrict__ w2)
{
    int q = blockIdx.x * blockDim.x + threadIdx.x;
    if (q >= Q_TOT) return;
    const float* src;
    __half* dst;
    int idx;
    if (q < Q_EMB)                       { src = emb;  dst = g_emb_h;  idx = q; }
    else if (q < Q_EMB+Q_WIN)            { src = win;  dst = g_win_h;  idx = q - Q_EMB;
        int row = (idx * 4) / DMODEL;
        if (row >= DINPROJ) {
            __half2* d = (__half2*)&dst[idx * 4];
            d[0] = __half2(__float2half(0.f), __float2half(0.f));
            d[1] = __half2(__float2half(0.f), __float2half(0.f));
            return;
        }
    }
    else if (q < Q_EMB+Q_WIN+Q_WOUT)     { src = wout; dst = g_wout_h; idx = q - (Q_EMB+Q_WIN); }
    else if (q < Q_EMB+Q_WIN+Q_WOUT+Q_W1){ src = w1;   dst = g_w1_h;   idx = q - (Q_EMB+Q_WIN+Q_WOUT); }
    else                                 { src = w2;   dst = g_w2_h;   idx = q - (Q_EMB+Q_WIN+Q_WOUT+Q_W1); }

    float4 v = *(const float4*)&src[idx * 4];
    __half2* d = (__half2*)&dst[idx * 4];
    d[0] = __float22half2_rn(make_float2(v.x, v.y));
    d[1] = __float22half2_rn(make_float2(v.z, v.w));
}

// ---------------- FP16 GEMM 128x128 (cp.async 4-stage) -----------------------
#define LDH 20
#define TILE_W (128 * LDH)
#define GEMM_SMEM (8 * TILE_W * 4)

template<int EPI, int OUTH>
__global__ __launch_bounds__(256, 2)
void h16gemm(const __half* __restrict__ A, const __half* __restrict__ B,
             const float* __restrict__ bias, void* __restrict__ Cv,
             int M, int N, int K)
{
    extern __shared__ uint32_t smemu[];
    uint32_t* AsB = smemu;
    uint32_t* BsB = smemu + 4 * TILE_W;

    const int tid = threadIdx.x;
    const int m0 = blockIdx.y * 128;
    const int n0 = blockIdx.x * 128;

    const int w    = tid >> 5;
    const int lane = tid & 31;
    const int wm   = (w >> 2) * 64;
    const int wn   = (w & 3) * 32;
    const int gr   = lane >> 2;
    const int gcw  = lane & 3;

    const int row0 = tid >> 2;
    const int c0   = tid & 3;

    uint32_t asb = (uint32_t)__cvta_generic_to_shared(AsB);
    uint32_t bsb = (uint32_t)__cvta_generic_to_shared(BsB);
    const uint32_t stg = TILE_W * 4;

    const uint32_t a_lane = (uint32_t)(((lane & 7) + ((lane >> 3) & 1) * 8) * 80
                                       + (lane >> 4) * 16);
    const uint32_t b_lane = (uint32_t)((lane & 15) * 80 + (lane >> 4) * 16);

    float acc[4][4][4];
    #pragma unroll
    for (int i = 0; i < 4; ++i)
        #pragma unroll
        for (int j = 0; j < 4; ++j)
            #pragma unroll
            for (int r = 0; r < 4; ++r) acc[i][j][r] = 0.0f;

    const int KT = K / 32;

    #pragma unroll
    for (int t = 0; t < 3; ++t) {
        if (t < KT) {
            size_t koff = (size_t)t * 32 + c0 * 8;
            #pragma unroll
            for (int i = 0; i < 2; ++i) {
                int row = row0 + i * 64;
                uint32_t doff = (uint32_t)t * stg + (uint32_t)(row * 80 + c0 * 16);
                cpasync16(asb + doff, A + (size_t)(m0 + row) * K + koff);
                cpasync16(bsb + doff, B + (size_t)(n0 + row) * K + koff);
            }
            cp_commit();
        }
    }

    for (int kt = 0; kt < KT; ++kt) {
        int rem = KT - 1 - kt;
        if (rem >= 2)      cp_wait2();
        else if (rem == 1) cp_wait1();
        else               cp_wait0();
        __syncthreads();

        if (kt + 3 < KT) {
            int nb = (kt + 3) & 3;
            size_t koff = (size_t)(kt + 3) * 32 + c0 * 8;
            #pragma unroll
            for (int i = 0; i < 2; ++i) {
                int row = row0 + i * 64;
                uint32_t doff = (uint32_t)nb * stg + (uint32_t)(row * 80 + c0 * 16);
                cpasync16(asb + doff, A + (size_t)(m0 + row) * K + koff);
                cpasync16(bsb + doff, B + (size_t)(n0 + row) * K + koff);
            }
            cp_commit();
        }

        const int cur = kt & 3;
        const uint32_t as_st = asb + (uint32_t)cur * stg;
        const uint32_t bs_st = bsb + (uint32_t)cur * stg;
        #pragma unroll
        for (int kk = 0; kk < 2; ++kk) {
            const uint32_t kb = (uint32_t)(kk * 32);
            uint32_t af[4][4];
            #pragma unroll
            for (int mi = 0; mi < 4; ++mi) {
                uint32_t sa = as_st + (uint32_t)((wm + mi * 16) * 80) + kb + a_lane;
                ldsm_x4(af[mi][0], af[mi][1], af[mi][2], af[mi][3], sa);
            }
            uint32_t bf[4][2];
            #pragma unroll
            for (int np = 0; np < 2; ++np) {
                uint32_t sb = bs_st + (uint32_t)((wn + np * 16) * 80) + kb + b_lane;
                ldsm_x4(bf[np*2][0], bf[np*2+1][0], bf[np*2][1], bf[np*2+1][1], sb);
            }
            #pragma unroll
            for (int mi = 0; mi < 4; ++mi)
                #pragma unroll
                for (int ni = 0; ni < 4; ++ni)
                    MMA16816(acc[mi][ni][0], acc[mi][ni][1], acc[mi][ni][2], acc[mi][ni][3],
                             af[mi][0], af[mi][1], af[mi][2], af[mi][3],
                             bf[ni][0], bf[ni][1]);
        }
    }

    float* Cf = (float*)Cv;
    __half* Ch = (__half*)Cv;
    #pragma unroll
    for (int mi = 0; mi < 4; ++mi) {
        int r = m0 + wm + mi * 16 + gr;
        #pragma unroll
        for (int ni = 0; ni < 4; ++ni) {
            int cb = n0 + wn + ni * 8 + 2 * gcw;
            #pragma unroll
            for (int half = 0; half < 2; ++half) {
                int rr = r + half * 8;
                float v0 = acc[mi][ni][half * 2 + 0];
                float v1 = acc[mi][ni][half * 2 + 1];
                if (cb < N) {
                    if (EPI >= 1) v0 += bias[cb];
                    if (EPI == 2) v0 = geluf(v0);
                    if (OUTH) Ch[(size_t)rr * N + cb] = __float2half_rn(v0);
                    else      Cf[(size_t)rr * N + cb] = v0;
                }
                if (cb + 1 < N) {
                    if (EPI >= 1) v1 += bias[cb + 1];
                    if (EPI == 2) v1 = geluf(v1);
                    if (OUTH) Ch[(size_t)rr * N + cb + 1] = __float2half_rn(v1);
                    else      Cf[(size_t)rr * N + cb + 1] = v1;
                }
            }
        }
    }
}

// ---------------- conv + silu + dt (fused, one launch) -----------------------
#define CONV_BLOCKS ((2 * NTOK * (CONVDIM/4) + 255) / 256)   // 2304
#define DT_BLOCKS   ((NTOK * NHEADS + 255) / 256)            // 512

__global__ void conv_dt_kernel(const float* __restrict__ conv_w,
                               const float* __restrict__ conv_b,
                               const float* __restrict__ dt_bias,
                               const float* __restrict__ A_log)
{
    if (blockIdx.x >= CONV_BLOCKS) {
        int e = (blockIdx.x - CONV_BLOCKS) * blockDim.x + threadIdx.x;
        if (e >= NTOK * NHEADS) return;
        int bt = e / NHEADS;
        int h  = e % NHEADS;
        float x = __half2float(g_zxh[(size_t)bt * DINPROJ + (DINNER + CONVDIM) + h]) + dt_bias[h];
        float dtv = softplusf(x);
        g_dt[e]  = dtv;
        g_ldA[e] = dtv * (-expf(A_log[h]));
        return;
    }

    int e = blockIdx.x * blockDim.x + threadIdx.x;
    const int C4 = CONVDIM / 4;
    const int total = 2 * NTOK * C4;
    if (e >= total) return;
    int dir = e / (NTOK * C4);
    int rem = e - dir * (NTOK * C4);
    int bt = rem / C4;
    int c4 = rem % C4;
    int b = bt / SEQLEN;
    int t = bt % SEQLEN;
    int c = c4 * 4;

    float4 w0 = *(const float4*)&conv_w[(c + 0) * 4];
    float4 w1 = *(const float4*)&conv_w[(c + 1) * 4];
    float4 w2 = *(const float4*)&conv_w[(c + 2) * 4];
    float4 w3 = *(const float4*)&conv_w[(c + 3) * 4];
    float4 acc = *(const float4*)&conv_b[c];

    float wt0[4] = {w0.x, w0.y, w0.z, w0.w};
    float wt1[4] = {w1.x, w1.y, w1.z, w1.w};
    float wt2[4] = {w2.x, w2.y, w2.z, w2.w};
    float wt3[4] = {w3.x, w3.y, w3.z, w3.w};

    #pragma unroll
    for (int k = 0; k < 4; ++k) {
        int tp = t - 3 + k;
        if (tp >= 0) {
            int s = dir ? (SEQLEN - 1 - tp) : tp;
            uint2 raw = *(const uint2*)&g_zxh[(size_t)(b * SEQLEN + s) * DINPROJ + DINNER + c];
            float2 v01 = __half22float2(*(__half2*)&raw.x);
            float2 v23 = __half22float2(*(__half2*)&raw.y);
            acc.x = fmaf(wt0[k], v01.x, acc.x);
            acc.y = fmaf(wt1[k], v01.y, acc.y);
            acc.z = fmaf(wt2[k], v23.x, acc.z);
            acc.w = fmaf(wt3[k], v23.y, acc.w);
        }
    }
    uint2 o;
    o.x = pack2h(siluf(acc.x), siluf(acc.y));
    o.y = pack2h(siluf(acc.z), siluf(acc.w));
    __half* out = dir ? g_xc1h : g_xc0h;
    *(uint2*)&out[(size_t)bt * CONVDIM + c] = o;
}

// ---------------- SSD pass A: chunk GEMMs (ldmatrix fragment loads) ----------
#define LDW 36   // uint32 words per smem row (144 bytes)

__global__ __launch_bounds__(128)
void ssd_chunk_mma_kernel(const float* __restrict__ Dp)
{
    __shared__ uint32_t Ck [64 * LDW];
    __shared__ uint32_t Bk [64 * LDW];
    __shared__ uint32_t Xt [64 * LDW];
    __shared__ uint32_t Btw[64 * LDW];
    __shared__ uint32_t Wsm[64 * LDW];
    __shared__ float sdt[64];
    __shared__ float slc[64];

    int blk   = blockIdx.x;
    int chunk = blk & 15;
    int h     = (blk >> 4) & 15;
    int b     = (blk >> 8) & 7;
    int dir   = blk >> 11;
    const int tid  = threadIdx.x;
    const int w    = tid >> 5;
    const int lane = tid & 31;
    const int gr   = lane >> 2;
    const int gcw  = lane & 3;
    const int wm   = w * 16;

    const __half* xch = dir ? g_xc1h : g_xc0h;
    float* yout = dir ? g_y1 : g_y0;
    const size_t hb = (size_t)(dir * BATCH + b) * NHEADS + h;
    const int t0 = chunk * CHUNK;

    const uint32_t ck_b  = (uint32_t)__cvta_generic_to_shared(Ck);
    const uint32_t bk_b  = (uint32_t)__cvta_generic_to_shared(Bk);
    const uint32_t xt_b  = (uint32_t)__cvta_generic_to_shared(Xt);
    const uint32_t btw_b = (uint32_t)__cvta_generic_to_shared(Btw);
    const uint32_t wsm_b = (uint32_t)__cvta_generic_to_shared(Wsm);
    const uint32_t aln = (uint32_t)(((lane & 7) + ((lane >> 3) & 1) * 8) * 144
                                    + (lane >> 4) * 16);
    const uint32_t bln = (uint32_t)((lane & 15) * 144 + (lane >> 4) * 16);

    if (tid < 64) {
        int t = t0 + tid;
        int s = dir ? (SEQLEN - 1 - t) : t;
        size_t de = (size_t)(b * SEQLEN + s) * NHEADS + h;
        sdt[tid] = g_dt[de];
        slc[tid] = g_ldA[de];
    }
    __syncthreads();
    #pragma unroll
    for (int off = 1; off < 64; off <<= 1) {
        float add = 0.0f;
        if (tid < 64 && tid >= off) add = slc[tid - off];
        __syncthreads();
        if (tid < 64) slc[tid] += add;
        __syncthreads();
    }
    if (tid < 64) g_cum[hb * SEQLEN + t0 + tid] = __expf(slc[tid]);
    __syncthreads();
    const float lcLast = slc[63];

    __half* XtH  = (__half*)Xt;
    __half* BtwH = (__half*)Btw;

    #pragma unroll
    for (int i = 0; i < 8; ++i) {
        int id = tid + i * 128;
        int row = id >> 4;
        int f4  = id & 15;
        size_t base = (size_t)(b * SEQLEN + t0 + row) * CONVDIM + DINNER;
        uint2 vb = *(const uint2*)&xch[base + f4 * 4];
        uint2 vc = *(const uint2*)&xch[base + DSTATE + f4 * 4];
        Bk[row * LDW + f4 * 2 + 0] = vb.x;
        Bk[row * LDW + f4 * 2 + 1] = vb.y;
        Ck[row * LDW + f4 * 2 + 0] = vc.x;
        Ck[row * LDW + f4 * 2 + 1] = vc.y;
    }
    #pragma unroll
    for (int i = 0; i < 8; ++i) {
        int id = tid + i * 128;
        int srow = id >> 4;
        int f4   = id & 15;
        size_t base = (size_t)(b * SEQLEN + t0 + srow) * CONVDIM;
        float w2f = sdt[srow] * __expf(lcLast - slc[srow]);
        __half2 w2h = __float2half2_rn(w2f);

        uint2 vx = *(const uint2*)&xch[base + h * HEADDIM + f4 * 4];
        __half2 x01 = *(__half2*)&vx.x;
        __half2 x23 = *(__half2*)&vx.y;
        XtH[(f4*4+0) * 72 + srow] = __low2half(x01);
        XtH[(f4*4+1) * 72 + srow] = __high2half(x01);
        XtH[(f4*4+2) * 72 + srow] = __low2half(x23);
        XtH[(f4*4+3) * 72 + srow] = __high2half(x23);

        uint2 vb = *(const uint2*)&xch[base + DINNER + f4 * 4];
        __half2 b01 = __hmul2(*(__half2*)&vb.x, w2h);
        __half2 b23 = __hmul2(*(__half2*)&vb.y, w2h);
        BtwH[(f4*4+0) * 72 + srow] = __low2half(b01);
        BtwH[(f4*4+1) * 72 + srow] = __high2half(b01);
        BtwH[(f4*4+2) * 72 + srow] = __low2half(b23);
        BtwH[(f4*4+3) * 72 + srow] = __high2half(b23);
    }
    __syncthreads();

    // GEMM 1: G = Ck @ Bk^T  (ldmatrix fragments)
    {
        float acc[8][4];
        #pragma unroll
        for (int j = 0; j < 8; ++j)
            #pragma unroll
            for (int r = 0; r < 4; ++r) acc[j][r] = 0.0f;

        #pragma unroll
        for (int kk = 0; kk < 4; ++kk) {
            const uint32_t kb = (uint32_t)(kk * 32);
            uint32_t af[4];
            ldsm_x4(af[0], af[1], af[2], af[3], ck_b + (uint32_t)(wm * 144) + kb + aln);
            uint32_t bf[8][2];
            #pragma unroll
            for (int np = 0; np < 4; ++np)
                ldsm_x4(bf[np*2][0], bf[np*2+1][0], bf[np*2][1], bf[np*2+1][1],
                        bk_b + (uint32_t)(np * 16 * 144) + kb + bln);
            #pragma unroll
            for (int ni = 0; ni < 8; ++ni)
                MMA16816(acc[ni][0], acc[ni][1], acc[ni][2], acc[ni][3],
                         af[0], af[1], af[2], af[3], bf[ni][0], bf[ni][1]);
        }

        int t_r0 = wm + gr, t_r1 = wm + gr + 8;
        float lt0 = slc[t_r0], lt1 = slc[t_r1];
        #pragma unroll
        for (int ni = 0; ni < 8; ++ni) {
            int s0 = ni * 8 + 2 * gcw;
            int s1 = s0 + 1;
            float ls0 = slc[s0], ls1 = slc[s1];
            float d0 = sdt[s0],  d1 = sdt[s1];
            float w00 = (s0 <= t_r0) ? __expf(lt0 - ls0) * d0 * acc[ni][0] : 0.0f;
            float w01 = (s1 <= t_r0) ? __expf(lt0 - ls1) * d1 * acc[ni][1] : 0.0f;
            float w10 = (s0 <= t_r1) ? __expf(lt1 - ls0) * d0 * acc[ni][2] : 0.0f;
            float w11 = (s1 <= t_r1) ? __expf(lt1 - ls1) * d1 * acc[ni][3] : 0.0f;
            Wsm[t_r0 * LDW + ni * 4 + gcw] = pack2h(w00, w01);
            Wsm[t_r1 * LDW + ni * 4 + gcw] = pack2h(w10, w11);
        }
    }
    __syncthreads();

    // GEMM 2: Y = W @ X
    {
        float acc[8][4];
        #pragma unroll
        for (int j = 0; j < 8; ++j)
            #pragma unroll
            for (int r = 0; r < 4; ++r) acc[j][r] = 0.0f;

        #pragma unroll
        for (int kk = 0; kk < 4; ++kk) {
            const uint32_t kb = (uint32_t)(kk * 32);
            uint32_t af[4];
            ldsm_x4(af[0], af[1], af[2], af[3], wsm_b + (uint32_t)(wm * 144) + kb + aln);
            uint32_t bf[8][2];
            #pragma unroll
            for (int np = 0; np < 4; ++np)
                ldsm_x4(bf[np*2][0], bf[np*2+1][0], bf[np*2][1], bf[np*2+1][1],
                        xt_b + (uint32_t)(np * 16 * 144) + kb + bln);
            #pragma unroll
            for (int ni = 0; ni < 8; ++ni)
                MMA16816(acc[ni][0], acc[ni][1], acc[ni][2], acc[ni][3],
                         af[0], af[1], af[2], af[3], bf[ni][0], bf[ni][1]);
        }

        float Dh = Dp[h];
        int t_r0 = wm + gr, t_r1 = t_r0 + 8;
        size_t yb0 = (size_t)(b * SEQLEN + t0 + t_r0) * DINNER + h * HEADDIM;
        size_t yb1 = (size_t)(b * SEQLEN + t0 + t_r1) * DINNER + h * HEADDIM;
        #pragma unroll
        for (int ni = 0; ni < 8; ++ni) {
            int p0 = ni * 8 + 2 * gcw;
            float x00 = __half2float(XtH[p0 * 72 + t_r0]);
            float x01 = __half2float(XtH[(p0+1) * 72 + t_r0]);
            float x10 = __half2float(XtH[p0 * 72 + t_r1]);
            float x11 = __half2float(XtH[(p0+1) * 72 + t_r1]);
            yout[yb0 + p0]     = acc[ni][0] + Dh * x00;
            yout[yb0 + p0 + 1] = acc[ni][1] + Dh * x01;
            yout[yb1 + p0]     = acc[ni][2] + Dh * x10;
            yout[yb1 + p0 + 1] = acc[ni][3] + Dh * x11;
        }
    }

    // GEMM 3: S[p][n] = Xt[p][s] @ Btw[n][s]^T
    {
        float acc[8][4];
        #pragma unroll
        for (int j = 0; j < 8; ++j)
            #pragma unroll
            for (int r = 0; r < 4; ++r) acc[j][r] = 0.0f;

        #pragma unroll
        for (int kk = 0; kk < 4; ++kk) {
            const uint32_t kb = (uint32_t)(kk * 32);
            uint32_t af[4];
            ldsm_x4(af[0], af[1], af[2], af[3], xt_b + (uint32_t)(wm * 144) + kb + aln);
            uint32_t bf[8][2];
            #pragma unroll
            for (int np = 0; np < 4; ++np)
                ldsm_x4(bf[np*2][0], bf[np*2+1][0], bf[np*2][1], bf[np*2+1][1],
                        btw_b + (uint32_t)(np * 16 * 144) + kb + bln);
            #pragma unroll
            for (int ni = 0; ni < 8; ++ni)
                MMA16816(acc[ni][0], acc[ni][1], acc[ni][2], acc[ni][3],
                         af[0], af[1], af[2], af[3], bf[ni][0], bf[ni][1]);
        }

        size_t lb = ((hb * NCHUNK) + chunk) * (HEADDIM * DSTATE);
        int p0 = wm + gr, p1 = p0 + 8;
        #pragma unroll
        for (int ni = 0; ni < 8; ++ni) {
            int n0 = ni * 8 + 2 * gcw;
            *(float2*)&g_L[lb + (size_t)p0 * DSTATE + n0] = make_float2(acc[ni][0], acc[ni][1]);
            *(float2*)&g_L[lb + (size_t)p1 * DSTATE + n0] = make_float2(acc[ni][2], acc[ni][3]);
        }
    }
}

// ---------------- SSD pass B: sequential chunk-state combine -----------------
__global__ __launch_bounds__(64)
void ssd_combine_kernel()
{
    int blk = blockIdx.x;
    int h   = blk & 15;
    int b   = (blk >> 4) & 7;
    int dir = blk >> 7;
    int p   = threadIdx.x;

    const size_t hb = (size_t)(dir * BATCH + b) * NHEADS + h;

    float H[64];
    #pragma unroll
    for (int n = 0; n < 64; ++n) H[n] = 0.0f;

    for (int c = 0; c < NCHUNK; ++c) {
        size_t off = ((hb * NCHUNK) + c) * (HEADDIM * DSTATE) + (size_t)p * DSTATE;
        #pragma unroll
        for (int q = 0; q < 16; ++q)
            *(float4*)&g_Hi[off + q * 4] = make_float4(H[q*4], H[q*4+1], H[q*4+2], H[q*4+3]);
        if (c < NCHUNK - 1) {
            float P = g_cum[hb * SEQLEN + c * CHUNK + CHUNK - 1];
            #pragma unroll
            for (int q = 0; q < 16; ++q) {
                float4 L = *(const float4*)&g_L[off + q * 4];
                H[q*4+0] = fmaf(H[q*4+0], P, L.x);
                H[q*4+1] = fmaf(H[q*4+1], P, L.y);
                H[q*4+2] = fmaf(H[q*4+2], P, L.z);
                H[q*4+3] = fmaf(H[q*4+3], P, L.w);
            }
        }
    }
}

// ---------------- SSD pass C: fixup (MMA, ldmatrix) --------------------------
__global__ __launch_bounds__(128)
void ssd_fixup_mma_kernel()
{
    __shared__ uint32_t Ash[64 * LDW];
    __shared__ uint32_t Bsh[64 * LDW];

    int idx  = blockIdx.x;
    int chunk = (idx % (NCHUNK - 1)) + 1;
    idx /= (NCHUNK - 1);
    int h   = idx & 15;
    int b   = (idx >> 4) & 7;
    int dir = idx >> 7;

    const __half* xch = dir ? g_xc1h : g_xc0h;
    float* yout = dir ? g_y1 : g_y0;
    const size_t hb = (size_t)(dir * BATCH + b) * NHEADS + h;
    const int t0 = chunk * CHUNK;
    const int tid = threadIdx.x;
    const int w    = tid >> 5;
    const int lane = tid & 31;
    const int gr   = lane >> 2;
    const int gcw  = lane & 3;
    const int wm   = w * 16;

    const uint32_t ash_b = (uint32_t)__cvta_generic_to_shared(Ash);
    const uint32_t bsh_b = (uint32_t)__cvta_generic_to_shared(Bsh);
    const uint32_t aln = (uint32_t)(((lane & 7) + ((lane >> 3) & 1) * 8) * 144
                                    + (lane >> 4) * 16);
    const uint32_t bln = (uint32_t)((lane & 15) * 144 + (lane >> 4) * 16);

    #pragma unroll
    for (int i = 0; i < 8; ++i) {
        int id = tid + i * 128;
        int row = id >> 4;
        int f4  = id & 15;
        uint2 v = *(const uint2*)&xch[(size_t)(b * SEQLEN + t0 + row) * CONVDIM
                                      + DINNER + DSTATE + f4 * 4];
        Ash[row * LDW + f4 * 2 + 0] = v.x;
        Ash[row * LDW + f4 * 2 + 1] = v.y;
    }
    {
        size_t hbase = ((hb * NCHUNK) + chunk) * (HEADDIM * DSTATE);
        #pragma unroll
        for (int i = 0; i < 8; ++i) {
            int id = tid + i * 128;
            int row = id >> 4;
            int f4  = id & 15;
            float4 v = *(const float4*)&g_Hi[hbase + (size_t)row * DSTATE + f4 * 4];
            Bsh[row * LDW + f4 * 2 + 0] = pack2h(v.x, v.y);
            Bsh[row * LDW + f4 * 2 + 1] = pack2h(v.z, v.w);
        }
    }
    __syncthreads();

    float acc[8][4];
    #pragma unroll
    for (int j = 0; j < 8; ++j)
        #pragma unroll
        for (int r = 0; r < 4; ++r) acc[j][r] = 0.0f;

    #pragma unroll
    for (int kk = 0; kk < 4; ++kk) {
        const uint32_t kb = (uint32_t)(kk * 32);
        uint32_t af[4];
        ldsm_x4(af[0], af[1], af[2], af[3], ash_b + (uint32_t)(wm * 144) + kb + aln);
        uint32_t bf[8][2];
        #pragma unroll
        for (int np = 0; np < 4; ++np)
            ldsm_x4(bf[np*2][0], bf[np*2+1][0], bf[np*2][1], bf[np*2+1][1],
                    bsh_b + (uint32_t)(np * 16 * 144) + kb + bln);
        #pragma unroll
        for (int ni = 0; ni < 8; ++ni)
            MMA16816(acc[ni][0], acc[ni][1], acc[ni][2], acc[ni][3],
                     af[0], af[1], af[2], af[3], bf[ni][0], bf[ni][1]);
    }

    int t_r0 = wm + gr, t_r1 = t_r0 + 8;
    float cum0 = g_cum[hb * SEQLEN + t0 + t_r0];
    float cum1 = g_cum[hb * SEQLEN + t0 + t_r1];
    size_t yb0 = (size_t)(b * SEQLEN + t0 + t_r0) * DINNER + h * HEADDIM;
    size_t yb1 = (size_t)(b * SEQLEN + t0 + t_r1) * DINNER + h * HEADDIM;
    #pragma unroll
    for (int ni = 0; ni < 8; ++ni) {
        int p0 = ni * 8 + 2 * gcw;
        yout[yb0 + p0]     += cum0 * acc[ni][0];
        yout[yb0 + p0 + 1] += cum0 * acc[ni][1];
        yout[yb1 + p0]     += cum1 * acc[ni][2];
        yout[yb1 + p0 + 1] += cum1 * acc[ni][3];
    }
}

// ---------------- gate + RMS + combine (fp32 y, fp16 z, fp16 G out) ----------
__global__ __launch_bounds__(256)
void gate_rms_combine_kernel(const float* __restrict__ norm_w)
{
    __shared__ float sdata[256];
    int bt = blockIdx.x;
    int b = bt / SEQLEN;
    int t = bt % SEQLEN;
    int tid = threadIdx.x;

    float gf[4], gb[4];
    float ssf = 0.0f, ssb = 0.0f;
    size_t zf = (size_t)bt * DINPROJ;
    size_t zb = (size_t)(b * SEQLEN + (SEQLEN - 1 - t)) * DINPROJ;
    #pragma unroll
    for (int i = 0; i < 4; ++i) {
        int j = tid + i * 256;
        float yv = g_y0[(size_t)bt * DINNER + j];
        float zv = __half2float(g_zxh[zf + j]);
        gf[i] = yv * siluf(zv);
        ssf = fmaf(gf[i], gf[i], ssf);

        float yv2 = g_y1[(size_t)bt * DINNER + j];
        float zv2 = __half2float(g_zxh[zb + j]);
        gb[i] = yv2 * siluf(zv2);
        ssb = fmaf(gb[i], gb[i], ssb);
    }
    float sumf = blockReduceSum(ssf, sdata);
    float sumb = blockReduceSum(ssb, sdata);
    float rf = rsqrtf(sumf / DINNER + 1e-5f);
    float rb = rsqrtf(sumb / DINNER + 1e-5f);

    #pragma unroll
    for (int i = 0; i < 4; ++i) {
        int j = tid + i * 256;
        float v = (gf[i] * rf + BETA * gb[i] * rb) * norm_w[j];
        g_Gh[(size_t)bt * DINNER + j] = __float2half_rn(v);
    }
}

// ---------------- LN1 ---------------------------------------------------------
__global__ __launch_bounds__(256)
void ln1_kernel(const float* __restrict__ emb,
                const float* __restrict__ w, const float* __restrict__ bln)
{
    __shared__ float sdata[256];
    int bt = blockIdx.x;
    int tid = threadIdx.x;
    size_t base = (size_t)bt * DMODEL;

    float v[2], s = 0.0f, sq = 0.0f;
    #pragma unroll
    for (int i = 0; i < 2; ++i) {
        int j = tid + i * 256;
        v[i] = g_O[base + j] + emb[base + j];
        s += v[i];
        sq = fmaf(v[i], v[i], sq);
    }
    float sum = blockReduceSum(s, sdata);
    float sumsq = blockReduceSum(sq, sdata);
    float mu = sum / DMODEL;
    float var = sumsq / DMODEL - mu * mu;
    float rs = rsqrtf(var + 1e-12f);
    #pragma unroll
    for (int i = 0; i < 2; ++i) {
        int j = tid + i * 256;
        float o = (v[i] - mu) * rs * w[j] + bln[j];
        g_Xln[base + j] = o;
        g_Xh [base + j] = __float2half_rn(o);
    }
}

// ---------------- LN2 ---------------------------------------------------------
__global__ __launch_bounds__(256)
void ln2_kernel(float* __restrict__ out,
                const float* __restrict__ w, const float* __restrict__ bln)
{
    __shared__ float sdata[256];
    int bt = blockIdx.x;
    int tid = threadIdx.x;
    size_t base = (size_t)bt * DMODEL;

    float v[2], s = 0.0f, sq = 0.0f;
    #pragma unroll
    for (int i = 0; i < 2; ++i) {
        int j = tid + i * 256;
        v[i] = g_H2[base + j] + g_Xln[base + j];
        s += v[i];
        sq = fmaf(v[i], v[i], sq);
    }
    float sum = blockReduceSum(s, sdata);
    float sumsq = blockReduceSum(sq, sdata);
    float mu = sum / DMODEL;
    float var = sumsq / DMODEL - mu * mu;
    float rs = rsqrtf(var + 1e-12f);
    #pragma unroll
    for (int i = 0; i < 2; ++i) {
        int j = tid + i * 256;
        out[base + j] = (v[i] - mu) * rs * w[j] + bln[j];
    }
}

// ---------------- launch -----------------------------------------------------
extern "C" void kernel_launch(void* const* d_in, const int* in_sizes, int n_in,
                              void* d_out, int out_size)
{
    const float* item_emb   = (const float*)d_in[0];
    const float* in_proj_w  = (const float*)d_in[3];
    const float* conv_w     = (const float*)d_in[4];
    const float* conv_b     = (const float*)d_in[5];
    const float* dt_bias    = (const float*)d_in[6];
    const float* A_log      = (const float*)d_in[7];
    const float* Dp         = (const float*)d_in[8];
    const float* norm_w     = (const float*)d_in[9];
    const float* out_proj_w = (const float*)d_in[10];
    const float* ln_w       = (const float*)d_in[11];
    const float* ln_b       = (const float*)d_in[12];
    const float* ffn_w1     = (const float*)d_in[13];
    const float* ffn_b1     = (const float*)d_in[14];
    const float* ffn_w2     = (const float*)d_in[15];
    const float* ffn_b2     = (const float*)d_in[16];
    const float* ffn_ln_w   = (const float*)d_in[17];
    const float* ffn_ln_b   = (const float*)d_in[18];
    float* out = (float*)d_out;

    float *p_O, *p_H2;
    __half *p_zxh, *p_embh, *p_Gh, *p_Xh, *p_H1h, *p_winh, *p_wouth, *p_w1h, *p_w2h;
    cudaGetSymbolAddress((void**)&p_zxh,  g_zxh);
    cudaGetSymbolAddress((void**)&p_O,    g_O);
    cudaGetSymbolAddress((void**)&p_H2,   g_H2);
    cudaGetSymbolAddress((void**)&p_embh, g_emb_h);
    cudaGetSymbolAddress((void**)&p_Gh,   g_Gh);
    cudaGetSymbolAddress((void**)&p_Xh,   g_Xh);
    cudaGetSymbolAddress((void**)&p_H1h,  g_H1h);
    cudaGetSymbolAddress((void**)&p_winh, g_win_h);
    cudaGetSymbolAddress((void**)&p_wouth,g_wout_h);
    cudaGetSymbolAddress((void**)&p_w1h,  g_w1_h);
    cudaGetSymbolAddress((void**)&p_w2h,  g_w2_h);

    cudaFuncSetAttribute(h16gemm<0,0>, cudaFuncAttributeMaxDynamicSharedMemorySize, GEMM_SMEM);
    cudaFuncSetAttribute(h16gemm<0,1>, cudaFuncAttributeMaxDynamicSharedMemorySize, GEMM_SMEM);
    cudaFuncSetAttribute(h16gemm<2,1>, cudaFuncAttributeMaxDynamicSharedMemorySize, GEMM_SMEM);
    cudaFuncSetAttribute(h16gemm<1,0>, cudaFuncAttributeMaxDynamicSharedMemorySize, GEMM_SMEM);

    // 0) all fp16 conversions in ONE launch
    cvt_all_kernel<<<(Q_TOT + 255) / 256, 256>>>(item_emb, in_proj_w, out_proj_w,
                                                 ffn_w1, ffn_w2);

    // 1) in_proj (8192 x 2192 x 512) -> fp16
    {
        dim3 grid(DINPROJ_PAD / 128, NTOK / 128);
        h16gemm<0,1><<<grid, 256, GEMM_SMEM>>>(p_embh, p_winh, nullptr, p_zxh, NTOK, DINPROJ, DMODEL);
    }

    // 2+3) conv + silu + dt (fused)
    conv_dt_kernel<<<CONV_BLOCKS + DT_BLOCKS, 256>>>(conv_w, conv_b, dt_bias, A_log);

    // 4) SSD: chunk GEMMs, combine, fixup
    ssd_chunk_mma_kernel<<<2*BATCH*NHEADS*NCHUNK, 128>>>(Dp);
    ssd_combine_kernel<<<256, 64>>>();
    ssd_fixup_mma_kernel<<<2*BATCH*NHEADS*(NCHUNK-1), 128>>>();

    // 5) gate + RMS + combine -> fp16 G
    gate_rms_combine_kernel<<<NTOK, 256>>>(norm_w);

    // 6) out_proj (8192 x 512 x 1024)
    {
        dim3 grid(DMODEL / 128, NTOK / 128);
        h16gemm<0,0><<<grid, 256, GEMM_SMEM>>>(p_Gh, p_wouth, nullptr, p_O, NTOK, DMODEL, DINNER);
    }

    // 7) LN1
    ln1_kernel<<<NTOK, 256>>>(item_emb, ln_w, ln_b);

    // 8) FFN1 (8192 x 2048 x 512)
    {
        dim3 grid(DFFN / 128, NTOK / 128);
        h16gemm<2,1><<<grid, 256, GEMM_SMEM>>>(p_Xh, p_w1h, ffn_b1, p_H1h, NTOK, DFFN, DMODEL);
    }

    // 9) FFN2 (8192 x 512 x 2048)
    {
        dim3 grid(DMODEL / 128, NTOK / 128);
        h16gemm<1,0><<<grid, 256, GEMM_SMEM>>>(p_H1h, p_w2h, ffn_b2, p_H2, NTOK, DMODEL, DFFN);
    }

    // 10) final LN
    ln2_kernel<<<NTOK, 256>>>(out, ffn_ln_w, ffn_ln_b);
}

// round 17
// speedup vs baseline: 1.1569x; 1.0362x over previous
#include <cuda_runtime.h>
#include <cuda_fp16.h>
#include <math.h>
#include <stdint.h>

#define BATCH   8
#define SEQLEN  1024
#define NTOK    (BATCH*SEQLEN)     // 8192
#define DMODEL  512
#define DSTATE  64
#define DINNER  1024
#define NHEADS  16
#define HEADDIM 64
#define DINPROJ 2192
#define DINPROJ_PAD 2304
#define CONVDIM 1152
#define DFFN    2048
#define BETA    0.5f
#define CHUNK   64
#define NCHUNK  16

// ---------------- scratch ----------------------------------------------------
__device__ __half g_zxh[NTOK*DINPROJ];
__device__ __half g_xc0h[NTOK*CONVDIM];
__device__ __half g_xc1h[NTOK*CONVDIM];
__device__ float  g_dt [NTOK*NHEADS];
__device__ float  g_ldA[NTOK*NHEADS];
__device__ float  g_y0 [NTOK*DINNER];
__device__ float  g_y1 [NTOK*DINNER];
__device__ float  g_O  [NTOK*DMODEL];
__device__ float  g_Xln[NTOK*DMODEL];
__device__ float  g_H2 [NTOK*DMODEL];
__device__ float  g_cum[2*BATCH*NHEADS*SEQLEN];
__device__ float  g_L  [2*BATCH*NHEADS*NCHUNK*HEADDIM*DSTATE];
__device__ float  g_Hi [2*BATCH*NHEADS*NCHUNK*HEADDIM*DSTATE];
// fp16 operands
__device__ __half g_emb_h[NTOK*DMODEL];
__device__ __half g_Gh   [NTOK*DINNER];
__device__ __half g_Xh   [NTOK*DMODEL];
__device__ __half g_H1h  [NTOK*DFFN];
__device__ __half g_win_h [DINPROJ_PAD*DMODEL];
__device__ __half g_wout_h[DMODEL*DINNER];
__device__ __half g_w1_h  [DFFN*DMODEL];
__device__ __half g_w2_h  [DMODEL*DFFN];

// ---------------- helpers ----------------------------------------------------
__device__ __forceinline__ float siluf(float v) {
    return v * __frcp_rn(1.0f + __expf(-v));
}
__device__ __forceinline__ float geluf(float v) { return 0.5f * v * (1.0f + erff(v * 0.70710678118654752f)); }
__device__ __forceinline__ float softplusf(float x) { return fmaxf(x, 0.0f) + log1pf(expf(-fabsf(x))); }

__device__ __forceinline__ void cpasync16(uint32_t saddr, const void* gptr) {
    asm volatile("cp.async.cg.shared.global [%0], [%1], 16;\n" :: "r"(saddr), "l"(gptr));
}
__device__ __forceinline__ void cp_commit() { asm volatile("cp.async.commit_group;\n"); }
__device__ __forceinline__ void cp_wait0()  { asm volatile("cp.async.wait_group 0;\n"); }
__device__ __forceinline__ void cp_wait1()  { asm volatile("cp.async.wait_group 1;\n"); }
__device__ __forceinline__ void cp_wait2()  { asm volatile("cp.async.wait_group 2;\n"); }

__device__ __forceinline__ void ldsm_x4(uint32_t& r0, uint32_t& r1, uint32_t& r2, uint32_t& r3,
                                        uint32_t saddr) {
    asm volatile("ldmatrix.sync.aligned.m8n8.x4.shared.b16 {%0,%1,%2,%3}, [%4];"
        : "=r"(r0), "=r"(r1), "=r"(r2), "=r"(r3) : "r"(saddr));
}
__device__ __forceinline__ void ldsm_x4_t(uint32_t& r0, uint32_t& r1, uint32_t& r2, uint32_t& r3,
                                          uint32_t saddr) {
    asm volatile("ldmatrix.sync.aligned.m8n8.x4.trans.shared.b16 {%0,%1,%2,%3}, [%4];"
        : "=r"(r0), "=r"(r1), "=r"(r2), "=r"(r3) : "r"(saddr));
}

#define MMA16816(d0,d1,d2,d3,a0,a1,a2,a3,b0,b1) \
    asm volatile( \
        "mma.sync.aligned.m16n8k16.row.col.f32.f16.f16.f32 " \
        "{%0,%1,%2,%3}, {%4,%5,%6,%7}, {%8,%9}, {%0,%1,%2,%3};" \
        : "+f"(d0), "+f"(d1), "+f"(d2), "+f"(d3) \
        : "r"(a0), "r"(a1), "r"(a2), "r"(a3), "r"(b0), "r"(b1))

__device__ __forceinline__ float blockReduceSum(float v, float* sdata) {
    int tid = threadIdx.x;
    sdata[tid] = v; __syncthreads();
    for (int s = blockDim.x >> 1; s > 0; s >>= 1) {
        if (tid < s) sdata[tid] += sdata[tid + s];
        __syncthreads();
    }
    float r = sdata[0]; __syncthreads();
    return r;
}
__device__ __forceinline__ uint32_t pack2h(float x, float y) {
    __half2 h = __float22half2_rn(make_float2(x, y));
    return *(uint32_t*)&h;
}

// ---------------- fused fp32 -> fp16 converter (one launch) ------------------
#define Q_EMB  (NTOK*DMODEL/4)
#define Q_WIN  (DINPROJ_PAD*DMODEL/4)
#define Q_WOUT (DMODEL*DINNER/4)
#define Q_W1   (DFFN*DMODEL/4)
#define Q_W2   (DMODEL*DFFN/4)
#define Q_TOT  (Q_EMB+Q_WIN+Q_WOUT+Q_W1+Q_W2)

__global__ void cvt_all_kernel(const float* __restrict__ emb,
                               const float* __restrict__ win,
                               const float* __restrict__ wout,
                               const float* __restrict__ w1,
                               const float* __restrict__ w2)
{
    int q = blockIdx.x * blockDim.x + threadIdx.x;
    if (q >= Q_TOT) return;
    const float* src;
    __half* dst;
    int idx;
    if (q < Q_EMB)                       { src = emb;  dst = g_emb_h;  idx = q; }
    else if (q < Q_EMB+Q_WIN)            { src = win;  dst = g_win_h;  idx = q - Q_EMB;
        int row = (idx * 4) / DMODEL;
        if (row >= DINPROJ) {
            __half2* d = (__half2*)&dst[idx * 4];
            d[0] = __half2(__float2half(0.f), __float2half(0.f));
            d[1] = __half2(__float2half(0.f), __float2half(0.f));
            return;
        }
    }
    else if (q < Q_EMB+Q_WIN+Q_WOUT)     { src = wout; dst = g_wout_h; idx = q - (Q_EMB+Q_WIN); }
    else if (q < Q_EMB+Q_WIN+Q_WOUT+Q_W1){ src = w1;   dst = g_w1_h;   idx = q - (Q_EMB+Q_WIN+Q_WOUT); }
    else                                 { src = w2;   dst = g_w2_h;   idx = q - (Q_EMB+Q_WIN+Q_WOUT+Q_W1); }

    float4 v = *(const float4*)&src[idx * 4];
    __half2* d = (__half2*)&dst[idx * 4];
    d[0] = __float22half2_rn(make_float2(v.x, v.y));
    d[1] = __float22half2_rn(make_float2(v.z, v.w));
}

// ---------------- FP16 GEMM 128x128 (cp.async 4-stage) -----------------------
#define LDH 20
#define TILE_W (128 * LDH)
#define GEMM_SMEM (8 * TILE_W * 4)

template<int EPI, int OUTH>
__global__ __launch_bounds__(256, 2)
void h16gemm(const __half* __restrict__ A, const __half* __restrict__ B,
             const float* __restrict__ bias, void* __restrict__ Cv,
             int M, int N, int K)
{
    extern __shared__ uint32_t smemu[];
    uint32_t* AsB = smemu;
    uint32_t* BsB = smemu + 4 * TILE_W;

    const int tid = threadIdx.x;
    const int m0 = blockIdx.y * 128;
    const int n0 = blockIdx.x * 128;

    const int w    = tid >> 5;
    const int lane = tid & 31;
    const int wm   = (w >> 2) * 64;
    const int wn   = (w & 3) * 32;
    const int gr   = lane >> 2;
    const int gcw  = lane & 3;

    const int row0 = tid >> 2;
    const int c0   = tid & 3;

    uint32_t asb = (uint32_t)__cvta_generic_to_shared(AsB);
    uint32_t bsb = (uint32_t)__cvta_generic_to_shared(BsB);
    const uint32_t stg = TILE_W * 4;

    const uint32_t a_lane = (uint32_t)(((lane & 7) + ((lane >> 3) & 1) * 8) * 80
                                       + (lane >> 4) * 16);
    const uint32_t b_lane = (uint32_t)((lane & 15) * 80 + (lane >> 4) * 16);

    float acc[4][4][4];
    #pragma unroll
    for (int i = 0; i < 4; ++i)
        #pragma unroll
        for (int j = 0; j < 4; ++j)
            #pragma unroll
            for (int r = 0; r < 4; ++r) acc[i][j][r] = 0.0f;

    const int KT = K / 32;

    #pragma unroll
    for (int t = 0; t < 3; ++t) {
        if (t < KT) {
            size_t koff = (size_t)t * 32 + c0 * 8;
            #pragma unroll
            for (int i = 0; i < 2; ++i) {
                int row = row0 + i * 64;
                uint32_t doff = (uint32_t)t * stg + (uint32_t)(row * 80 + c0 * 16);
                cpasync16(asb + doff, A + (size_t)(m0 + row) * K + koff);
                cpasync16(bsb + doff, B + (size_t)(n0 + row) * K + koff);
            }
            cp_commit();
        }
    }

    for (int kt = 0; kt < KT; ++kt) {
        int rem = KT - 1 - kt;
        if (rem >= 2)      cp_wait2();
        else if (rem == 1) cp_wait1();
        else               cp_wait0();
        __syncthreads();

        if (kt + 3 < KT) {
            int nb = (kt + 3) & 3;
            size_t koff = (size_t)(kt + 3) * 32 + c0 * 8;
            #pragma unroll
            for (int i = 0; i < 2; ++i) {
                int row = row0 + i * 64;
                uint32_t doff = (uint32_t)nb * stg + (uint32_t)(row * 80 + c0 * 16);
                cpasync16(asb + doff, A + (size_t)(m0 + row) * K + koff);
                cpasync16(bsb + doff, B + (size_t)(n0 + row) * K + koff);
            }
            cp_commit();
        }

        const int cur = kt & 3;
        const uint32_t as_st = asb + (uint32_t)cur * stg;
        const uint32_t bs_st = bsb + (uint32_t)cur * stg;
        #pragma unroll
        for (int kk = 0; kk < 2; ++kk) {
            const uint32_t kb = (uint32_t)(kk * 32);
            uint32_t af[4][4];
            #pragma unroll
            for (int mi = 0; mi < 4; ++mi) {
                uint32_t sa = as_st + (uint32_t)((wm + mi * 16) * 80) + kb + a_lane;
                ldsm_x4(af[mi][0], af[mi][1], af[mi][2], af[mi][3], sa);
            }
            uint32_t bf[4][2];
            #pragma unroll
            for (int np = 0; np < 2; ++np) {
                uint32_t sb = bs_st + (uint32_t)((wn + np * 16) * 80) + kb + b_lane;
                ldsm_x4(bf[np*2][0], bf[np*2+1][0], bf[np*2][1], bf[np*2+1][1], sb);
            }
            #pragma unroll
            for (int mi = 0; mi < 4; ++mi)
                #pragma unroll
                for (int ni = 0; ni < 4; ++ni)
                    MMA16816(acc[mi][ni][0], acc[mi][ni][1], acc[mi][ni][2], acc[mi][ni][3],
                             af[mi][0], af[mi][1], af[mi][2], af[mi][3],
                             bf[ni][0], bf[ni][1]);
        }
    }

    float* Cf = (float*)Cv;
    __half* Ch = (__half*)Cv;
    #pragma unroll
    for (int mi = 0; mi < 4; ++mi) {
        int r = m0 + wm + mi * 16 + gr;
        #pragma unroll
        for (int ni = 0; ni < 4; ++ni) {
            int cb = n0 + wn + ni * 8 + 2 * gcw;
            #pragma unroll
            for (int half = 0; half < 2; ++half) {
                int rr = r + half * 8;
                float v0 = acc[mi][ni][half * 2 + 0];
                float v1 = acc[mi][ni][half * 2 + 1];
                if (cb < N) {
                    if (EPI >= 1) v0 += bias[cb];
                    if (EPI == 2) v0 = geluf(v0);
                    if (OUTH) Ch[(size_t)rr * N + cb] = __float2half_rn(v0);
                    else      Cf[(size_t)rr * N + cb] = v0;
                }
                if (cb + 1 < N) {
                    if (EPI >= 1) v1 += bias[cb + 1];
                    if (EPI == 2) v1 = geluf(v1);
                    if (OUTH) Ch[(size_t)rr * N + cb + 1] = __float2half_rn(v1);
                    else      Cf[(size_t)rr * N + cb + 1] = v1;
                }
            }
        }
    }
}

// ---------------- conv + silu + dt (fused, one launch) -----------------------
#define CONV_BLOCKS ((2 * NTOK * (CONVDIM/4) + 255) / 256)
#define DT_BLOCKS   ((NTOK * NHEADS + 255) / 256)

__global__ void conv_dt_kernel(const float* __restrict__ conv_w,
                               const float* __restrict__ conv_b,
                               const float* __restrict__ dt_bias,
                               const float* __restrict__ A_log)
{
    if (blockIdx.x >= CONV_BLOCKS) {
        int e = (blockIdx.x - CONV_BLOCKS) * blockDim.x + threadIdx.x;
        if (e >= NTOK * NHEADS) return;
        int bt = e / NHEADS;
        int h  = e % NHEADS;
        float x = __half2float(g_zxh[(size_t)bt * DINPROJ + (DINNER + CONVDIM) + h]) + dt_bias[h];
        float dtv = softplusf(x);
        g_dt[e]  = dtv;
        g_ldA[e] = dtv * (-expf(A_log[h]));
        return;
    }

    int e = blockIdx.x * blockDim.x + threadIdx.x;
    const int C4 = CONVDIM / 4;
    const int total = 2 * NTOK * C4;
    if (e >= total) return;
    int dir = e / (NTOK * C4);
    int rem = e - dir * (NTOK * C4);
    int bt = rem / C4;
    int c4 = rem % C4;
    int b = bt / SEQLEN;
    int t = bt % SEQLEN;
    int c = c4 * 4;

    float4 w0 = *(const float4*)&conv_w[(c + 0) * 4];
    float4 w1 = *(const float4*)&conv_w[(c + 1) * 4];
    float4 w2 = *(const float4*)&conv_w[(c + 2) * 4];
    float4 w3 = *(const float4*)&conv_w[(c + 3) * 4];
    float4 acc = *(const float4*)&conv_b[c];

    float wt0[4] = {w0.x, w0.y, w0.z, w0.w};
    float wt1[4] = {w1.x, w1.y, w1.z, w1.w};
    float wt2[4] = {w2.x, w2.y, w2.z, w2.w};
    float wt3[4] = {w3.x, w3.y, w3.z, w3.w};

    #pragma unroll
    for (int k = 0; k < 4; ++k) {
        int tp = t - 3 + k;
        if (tp >= 0) {
            int s = dir ? (SEQLEN - 1 - tp) : tp;
            uint2 raw = *(const uint2*)&g_zxh[(size_t)(b * SEQLEN + s) * DINPROJ + DINNER + c];
            float2 v01 = __half22float2(*(__half2*)&raw.x);
            float2 v23 = __half22float2(*(__half2*)&raw.y);
            acc.x = fmaf(wt0[k], v01.x, acc.x);
            acc.y = fmaf(wt1[k], v01.y, acc.y);
            acc.z = fmaf(wt2[k], v23.x, acc.z);
            acc.w = fmaf(wt3[k], v23.y, acc.w);
        }
    }
    uint2 o;
    o.x = pack2h(siluf(acc.x), siluf(acc.y));
    o.y = pack2h(siluf(acc.z), siluf(acc.w));
    __half* out = dir ? g_xc1h : g_xc0h;
    *(uint2*)&out[(size_t)bt * CONVDIM + c] = o;
}

// ---------------- SSD pass A: chunk GEMMs (row staging + ldmatrix.trans) -----
#define LDW 36   // uint32 words per smem row (144 bytes)

__global__ __launch_bounds__(128)
void ssd_chunk_mma_kernel(const float* __restrict__ Dp)
{
    __shared__ uint32_t Ck [64 * LDW];    // C[t][n]; reused for W[t][s] after GEMM1
    __shared__ uint32_t Bk [64 * LDW];    // B[s][n]
    __shared__ uint32_t Xs [64 * LDW];    // X[s][p]  (row layout)
    __shared__ uint32_t Bw [64 * LDW];    // (B*w2)[s][n] (row layout)
    __shared__ float sdt[64];
    __shared__ float slc[64];

    int blk   = blockIdx.x;
    int chunk = blk & 15;
    int h     = (blk >> 4) & 15;
    int b     = (blk >> 8) & 7;
    int dir   = blk >> 11;
    const int tid  = threadIdx.x;
    const int w    = tid >> 5;
    const int lane = tid & 31;
    const int gr   = lane >> 2;
    const int gcw  = lane & 3;
    const int wm   = w * 16;

    const __half* xch = dir ? g_xc1h : g_xc0h;
    float* yout = dir ? g_y1 : g_y0;
    const size_t hb = (size_t)(dir * BATCH + b) * NHEADS + h;
    const int t0 = chunk * CHUNK;

    const uint32_t ck_b = (uint32_t)__cvta_generic_to_shared(Ck);
    const uint32_t bk_b = (uint32_t)__cvta_generic_to_shared(Bk);
    const uint32_t xs_b = (uint32_t)__cvta_generic_to_shared(Xs);
    const uint32_t bw_b = (uint32_t)__cvta_generic_to_shared(Bw);
    // non-trans A-fragment lane offset (rows m, 16B col groups)
    const uint32_t aln = (uint32_t)(((lane & 7) + ((lane >> 3) & 1) * 8) * 144
                                    + (lane >> 4) * 16);
    // row-address lane offset (16 rows x 2 col groups) — used for non-trans B
    // and all trans loads
    const uint32_t bln = (uint32_t)((lane & 15) * 144 + (lane >> 4) * 16);

    if (tid < 64) {
        int t = t0 + tid;
        int s = dir ? (SEQLEN - 1 - t) : t;
        size_t de = (size_t)(b * SEQLEN + s) * NHEADS + h;
        sdt[tid] = g_dt[de];
        slc[tid] = g_ldA[de];
    }
    __syncthreads();
    #pragma unroll
    for (int off = 1; off < 64; off <<= 1) {
        float add = 0.0f;
        if (tid < 64 && tid >= off) add = slc[tid - off];
        __syncthreads();
        if (tid < 64) slc[tid] += add;
        __syncthreads();
    }
    if (tid < 64) g_cum[hb * SEQLEN + t0 + tid] = __expf(slc[tid]);
    __syncthreads();
    const float lcLast = slc[63];

    __half* XsH = (__half*)Xs;

    // stage all four tiles with vector uint2 stores (row layout)
    #pragma unroll
    for (int i = 0; i < 8; ++i) {
        int id = tid + i * 128;
        int row = id >> 4;               // token index within chunk
        int f4  = id & 15;
        size_t base = (size_t)(b * SEQLEN + t0 + row) * CONVDIM;

        uint2 vb = *(const uint2*)&xch[base + DINNER + f4 * 4];
        uint2 vc = *(const uint2*)&xch[base + DINNER + DSTATE + f4 * 4];
        Bk[row * LDW + f4 * 2 + 0] = vb.x;
        Bk[row * LDW + f4 * 2 + 1] = vb.y;
        Ck[row * LDW + f4 * 2 + 0] = vc.x;
        Ck[row * LDW + f4 * 2 + 1] = vc.y;

        uint2 vx = *(const uint2*)&xch[base + h * HEADDIM + f4 * 4];
        Xs[row * LDW + f4 * 2 + 0] = vx.x;
        Xs[row * LDW + f4 * 2 + 1] = vx.y;

        float w2f = sdt[row] * __expf(lcLast - slc[row]);
        __half2 w2h = __float2half2_rn(w2f);
        __half2 b01 = __hmul2(*(__half2*)&vb.x, w2h);
        __half2 b23 = __hmul2(*(__half2*)&vb.y, w2h);
        Bw[row * LDW + f4 * 2 + 0] = *(uint32_t*)&b01;
        Bw[row * LDW + f4 * 2 + 1] = *(uint32_t*)&b23;
    }
    __syncthreads();

    // GEMM 1: G = C @ B^T  (A = Ck rows non-trans, B = Bk rows non-trans)
    float wacc[8][4];
    {
        #pragma unroll
        for (int j = 0; j < 8; ++j)
            #pragma unroll
            for (int r = 0; r < 4; ++r) wacc[j][r] = 0.0f;

        #pragma unroll
        for (int kk = 0; kk < 4; ++kk) {
            const uint32_t kb = (uint32_t)(kk * 32);
            uint32_t af[4];
            ldsm_x4(af[0], af[1], af[2], af[3], ck_b + (uint32_t)(wm * 144) + kb + aln);
            uint32_t bf[8][2];
            #pragma unroll
            for (int np = 0; np < 4; ++np)
                ldsm_x4(bf[np*2][0], bf[np*2+1][0], bf[np*2][1], bf[np*2+1][1],
                        bk_b + (uint32_t)(np * 16 * 144) + kb + bln);
            #pragma unroll
            for (int ni = 0; ni < 8; ++ni)
                MMA16816(wacc[ni][0], wacc[ni][1], wacc[ni][2], wacc[ni][3],
                         af[0], af[1], af[2], af[3], bf[ni][0], bf[ni][1]);
        }
    }
    __syncthreads();   // all warps done reading Ck — safe to overwrite with W

    // mask + weight -> W stored into Ck  [t][s]
    {
        int t_r0 = wm + gr, t_r1 = wm + gr + 8;
        float lt0 = slc[t_r0], lt1 = slc[t_r1];
        #pragma unroll
        for (int ni = 0; ni < 8; ++ni) {
            int s0 = ni * 8 + 2 * gcw;
            int s1 = s0 + 1;
            float ls0 = slc[s0], ls1 = slc[s1];
            float d0 = sdt[s0],  d1 = sdt[s1];
            float w00 = (s0 <= t_r0) ? __expf(lt0 - ls0) * d0 * wacc[ni][0] : 0.0f;
            float w01 = (s1 <= t_r0) ? __expf(lt0 - ls1) * d1 * wacc[ni][1] : 0.0f;
            float w10 = (s0 <= t_r1) ? __expf(lt1 - ls0) * d0 * wacc[ni][2] : 0.0f;
            float w11 = (s1 <= t_r1) ? __expf(lt1 - ls1) * d1 * wacc[ni][3] : 0.0f;
            Ck[t_r0 * LDW + ni * 4 + gcw] = pack2h(w00, w01);
            Ck[t_r1 * LDW + ni * 4 + gcw] = pack2h(w10, w11);
        }
    }
    __syncthreads();

    // GEMM 2: Y = W @ X   (A = Ck(W) non-trans; B = Xs rows, ldmatrix.trans)
    {
        float acc[8][4];
        #pragma unroll
        for (int j = 0; j < 8; ++j)
            #pragma unroll
            for (int r = 0; r < 4; ++r) acc[j][r] = 0.0f;

        #pragma unroll
        for (int kk = 0; kk < 4; ++kk) {
            const uint32_t kb = (uint32_t)(kk * 32);           // A: 16 halves along s
            const uint32_t krow = (uint32_t)(kk * 16 * 144);   // B: 16 s-rows
            uint32_t af[4];
            ldsm_x4(af[0], af[1], af[2], af[3], ck_b + (uint32_t)(wm * 144) + kb + aln);
            uint32_t bf[8][2];
            #pragma unroll
            for (int np = 0; np < 4; ++np) {
                uint32_t r0, r1, r2, r3;
                ldsm_x4_t(r0, r1, r2, r3, xs_b + krow + (uint32_t)(np * 32) + bln);
                bf[np*2][0] = r0;  bf[np*2][1] = r1;     // n 0-7 of group: kL,kH
                bf[np*2+1][0] = r2; bf[np*2+1][1] = r3;  // n 8-15
            }
            #pragma unroll
            for (int ni = 0; ni < 8; ++ni)
                MMA16816(acc[ni][0], acc[ni][1], acc[ni][2], acc[ni][3],
                         af[0], af[1], af[2], af[3], bf[ni][0], bf[ni][1]);
        }

        float Dh = Dp[h];
        int t_r0 = wm + gr, t_r1 = t_r0 + 8;
        size_t yb0 = (size_t)(b * SEQLEN + t0 + t_r0) * DINNER + h * HEADDIM;
        size_t yb1 = (size_t)(b * SEQLEN + t0 + t_r1) * DINNER + h * HEADDIM;
        #pragma unroll
        for (int ni = 0; ni < 8; ++ni) {
            int p0 = ni * 8 + 2 * gcw;
            // X in row layout: X[t][p] pair (p0, p0+1) is one aligned half2
            uint32_t xr0 = Xs[t_r0 * LDW + (p0 >> 1)];
            uint32_t xr1 = Xs[t_r1 * LDW + (p0 >> 1)];
            float2 x0 = __half22float2(*(__half2*)&xr0);
            float2 x1 = __half22float2(*(__half2*)&xr1);
            yout[yb0 + p0]     = acc[ni][0] + Dh * x0.x;
            yout[yb0 + p0 + 1] = acc[ni][1] + Dh * x0.y;
            yout[yb1 + p0]     = acc[ni][2] + Dh * x1.x;
            yout[yb1 + p0 + 1] = acc[ni][3] + Dh * x1.y;
        }
    }

    // GEMM 3: S[p][n] = X^T @ (B*w2)  (A = Xs trans; B = Bw trans)
    {
        float acc[8][4];
        #pragma unroll
        for (int j = 0; j < 8; ++j)
            #pragma unroll
            for (int r = 0; r < 4; ++r) acc[j][r] = 0.0f;

        #pragma unroll
        for (int kk = 0; kk < 4; ++kk) {
            const uint32_t krow = (uint32_t)(kk * 16 * 144);   // 16 s-rows
            uint32_t r0, r1, r2, r3;
            // A = X^T[p][s]: trans of X[s][p]; m offset = wm columns (bytes = wm*2)
            ldsm_x4_t(r0, r1, r2, r3, xs_b + krow + (uint32_t)(wm * 2) + bln);
            uint32_t af[4] = {r0, r2, r1, r3};   // reorder: {m0 kL, m8 kL, m0 kH, m8 kH}
            uint32_t bf[8][2];
            #pragma unroll
            for (int np = 0; np < 4; ++np) {
                uint32_t s0, s1, s2, s3;
                ldsm_x4_t(s0, s1, s2, s3, bw_b + krow + (uint32_t)(np * 32) + bln);
                bf[np*2][0] = s0;  bf[np*2][1] = s1;
                bf[np*2+1][0] = s2; bf[np*2+1][1] = s3;
            }
            #pragma unroll
            for (int ni = 0; ni < 8; ++ni)
                MMA16816(acc[ni][0], acc[ni][1], acc[ni][2], acc[ni][3],
                         af[0], af[1], af[2], af[3], bf[ni][0], bf[ni][1]);
        }

        size_t lb = ((hb * NCHUNK) + chunk) * (HEADDIM * DSTATE);
        int p0 = wm + gr, p1 = p0 + 8;
        #pragma unroll
        for (int ni = 0; ni < 8; ++ni) {
            int n0 = ni * 8 + 2 * gcw;
            *(float2*)&g_L[lb + (size_t)p0 * DSTATE + n0] = make_float2(acc[ni][0], acc[ni][1]);
            *(float2*)&g_L[lb + (size_t)p1 * DSTATE + n0] = make_float2(acc[ni][2], acc[ni][3]);
        }
    }
}

// ---------------- SSD pass B: sequential chunk-state combine -----------------
__global__ __launch_bounds__(64)
void ssd_combine_kernel()
{
    int blk = blockIdx.x;
    int h   = blk & 15;
    int b   = (blk >> 4) & 7;
    int dir = blk >> 7;
    int p   = threadIdx.x;

    const size_t hb = (size_t)(dir * BATCH + b) * NHEADS + h;

    float H[64];
    #pragma unroll
    for (int n = 0; n < 64; ++n) H[n] = 0.0f;

    for (int c = 0; c < NCHUNK; ++c) {
        size_t off = ((hb * NCHUNK) + c) * (HEADDIM * DSTATE) + (size_t)p * DSTATE;
        #pragma unroll
        for (int q = 0; q < 16; ++q)
            *(float4*)&g_Hi[off + q * 4] = make_float4(H[q*4], H[q*4+1], H[q*4+2], H[q*4+3]);
        if (c < NCHUNK - 1) {
            float P = g_cum[hb * SEQLEN + c * CHUNK + CHUNK - 1];
            #pragma unroll
            for (int q = 0; q < 16; ++q) {
                float4 L = *(const float4*)&g_L[off + q * 4];
                H[q*4+0] = fmaf(H[q*4+0], P, L.x);
                H[q*4+1] = fmaf(H[q*4+1], P, L.y);
                H[q*4+2] = fmaf(H[q*4+2], P, L.z);
                H[q*4+3] = fmaf(H[q*4+3], P, L.w);
            }
        }
    }
}

// ---------------- SSD pass C: fixup (MMA, ldmatrix) --------------------------
__global__ __launch_bounds__(128)
void ssd_fixup_mma_kernel()
{
    __shared__ uint32_t Ash[64 * LDW];
    __shared__ uint32_t Bsh[64 * LDW];

    int idx  = blockIdx.x;
    int chunk = (idx % (NCHUNK - 1)) + 1;
    idx /= (NCHUNK - 1);
    int h   = idx & 15;
    int b   = (idx >> 4) & 7;
    int dir = idx >> 7;

    const __half* xch = dir ? g_xc1h : g_xc0h;
    float* yout = dir ? g_y1 : g_y0;
    const size_t hb = (size_t)(dir * BATCH + b) * NHEADS + h;
    const int t0 = chunk * CHUNK;
    const int tid = threadIdx.x;
    const int w    = tid >> 5;
    const int lane = tid & 31;
    const int gr   = lane >> 2;
    const int gcw  = lane & 3;
    const int wm   = w * 16;

    const uint32_t ash_b = (uint32_t)__cvta_generic_to_shared(Ash);
    const uint32_t bsh_b = (uint32_t)__cvta_generic_to_shared(Bsh);
    const uint32_t aln = (uint32_t)(((lane & 7) + ((lane >> 3) & 1) * 8) * 144
                                    + (lane >> 4) * 16);
    const uint32_t bln = (uint32_t)((lane & 15) * 144 + (lane >> 4) * 16);

    #pragma unroll
    for (int i = 0; i < 8; ++i) {
        int id = tid + i * 128;
        int row = id >> 4;
        int f4  = id & 15;
        uint2 v = *(const uint2*)&xch[(size_t)(b * SEQLEN + t0 + row) * CONVDIM
                                      + DINNER + DSTATE + f4 * 4];
        Ash[row * LDW + f4 * 2 + 0] = v.x;
        Ash[row * LDW + f4 * 2 + 1] = v.y;
    }
    {
        size_t hbase = ((hb * NCHUNK) + chunk) * (HEADDIM * DSTATE);
        #pragma unroll
        for (int i = 0; i < 8; ++i) {
            int id = tid + i * 128;
            int row = id >> 4;
            int f4  = id & 15;
            float4 v = *(const float4*)&g_Hi[hbase + (size_t)row * DSTATE + f4 * 4];
            Bsh[row * LDW + f4 * 2 + 0] = pack2h(v.x, v.y);
            Bsh[row * LDW + f4 * 2 + 1] = pack2h(v.z, v.w);
        }
    }
    __syncthreads();

    float acc[8][4];
    #pragma unroll
    for (int j = 0; j < 8; ++j)
        #pragma unroll
        for (int r = 0; r < 4; ++r) acc[j][r] = 0.0f;

    #pragma unroll
    for (int kk = 0; kk < 4; ++kk) {
        const uint32_t kb = (uint32_t)(kk * 32);
        uint32_t af[4];
        ldsm_x4(af[0], af[1], af[2], af[3], ash_b + (uint32_t)(wm * 144) + kb + aln);
        uint32_t bf[8][2];
        #pragma unroll
        for (int np = 0; np < 4; ++np)
            ldsm_x4(bf[np*2][0], bf[np*2+1][0], bf[np*2][1], bf[np*2+1][1],
                    bsh_b + (uint32_t)(np * 16 * 144) + kb + bln);
        #pragma unroll
        for (int ni = 0; ni < 8; ++ni)
            MMA16816(acc[ni][0], acc[ni][1], acc[ni][2], acc[ni][3],
                     af[0], af[1], af[2], af[3], bf[ni][0], bf[ni][1]);
    }

    int t_r0 = wm + gr, t_r1 = t_r0 + 8;
    float cum0 = g_cum[hb * SEQLEN + t0 + t_r0];
    float cum1 = g_cum[hb * SEQLEN + t0 + t_r1];
    size_t yb0 = (size_t)(b * SEQLEN + t0 + t_r0) * DINNER + h * HEADDIM;
    size_t yb1 = (size_t)(b * SEQLEN + t0 + t_r1) * DINNER + h * HEADDIM;
    #pragma unroll
    for (int ni = 0; ni < 8; ++ni) {
        int p0 = ni * 8 + 2 * gcw;
        yout[yb0 + p0]     += cum0 * acc[ni][0];
        yout[yb0 + p0 + 1] += cum0 * acc[ni][1];
        yout[yb1 + p0]     += cum1 * acc[ni][2];
        yout[yb1 + p0 + 1] += cum1 * acc[ni][3];
    }
}

// ---------------- gate + RMS + combine (fp32 y, fp16 z, fp16 G out) ----------
__global__ __launch_bounds__(256)
void gate_rms_combine_kernel(const float* __restrict__ norm_w)
{
    __shared__ float sdata[256];
    int bt = blockIdx.x;
    int b = bt / SEQLEN;
    int t = bt % SEQLEN;
    int tid = threadIdx.x;

    float gf[4], gb[4];
    float ssf = 0.0f, ssb = 0.0f;
    size_t zf = (size_t)bt * DINPROJ;
    size_t zb = (size_t)(b * SEQLEN + (SEQLEN - 1 - t)) * DINPROJ;
    #pragma unroll
    for (int i = 0; i < 4; ++i) {
        int j = tid + i * 256;
        float yv = g_y0[(size_t)bt * DINNER + j];
        float zv = __half2float(g_zxh[zf + j]);
        gf[i] = yv * siluf(zv);
        ssf = fmaf(gf[i], gf[i], ssf);

        float yv2 = g_y1[(size_t)bt * DINNER + j];
        float zv2 = __half2float(g_zxh[zb + j]);
        gb[i] = yv2 * siluf(zv2);
        ssb = fmaf(gb[i], gb[i], ssb);
    }
    float sumf = blockReduceSum(ssf, sdata);
    float sumb = blockReduceSum(ssb, sdata);
    float rf = rsqrtf(sumf / DINNER + 1e-5f);
    float rb = rsqrtf(sumb / DINNER + 1e-5f);

    #pragma unroll
    for (int i = 0; i < 4; ++i) {
        int j = tid + i * 256;
        float v = (gf[i] * rf + BETA * gb[i] * rb) * norm_w[j];
        g_Gh[(size_t)bt * DINNER + j] = __float2half_rn(v);
    }
}

// ---------------- LN1 ---------------------------------------------------------
__global__ __launch_bounds__(256)
void ln1_kernel(const float* __restrict__ emb,
                const float* __restrict__ w, const float* __restrict__ bln)
{
    __shared__ float sdata[256];
    int bt = blockIdx.x;
    int tid = threadIdx.x;
    size_t base = (size_t)bt * DMODEL;

    float v[2], s = 0.0f, sq = 0.0f;
    #pragma unroll
    for (int i = 0; i < 2; ++i) {
        int j = tid + i * 256;
        v[i] = g_O[base + j] + emb[base + j];
        s += v[i];
        sq = fmaf(v[i], v[i], sq);
    }
    float sum = blockReduceSum(s, sdata);
    float sumsq = blockReduceSum(sq, sdata);
    float mu = sum / DMODEL;
    float var = sumsq / DMODEL - mu * mu;
    float rs = rsqrtf(var + 1e-12f);
    #pragma unroll
    for (int i = 0; i < 2; ++i) {
        int j = tid + i * 256;
        float o = (v[i] - mu) * rs * w[j] + bln[j];
        g_Xln[base + j] = o;
        g_Xh [base + j] = __float2half_rn(o);
    }
}

// ---------------- LN2 ---------------------------------------------------------
__global__ __launch_bounds__(256)
void ln2_kernel(float* __restrict__ out,
                const float* __restrict__ w, const float* __restrict__ bln)
{
    __shared__ float sdata[256];
    int bt = blockIdx.x;
    int tid = threadIdx.x;
    size_t base = (size_t)bt * DMODEL;

    float v[2], s = 0.0f, sq = 0.0f;
    #pragma unroll
    for (int i = 0; i < 2; ++i) {
        int j = tid + i * 256;
        v[i] = g_H2[base + j] + g_Xln[base + j];
        s += v[i];
        sq = fmaf(v[i], v[i], sq);
    }
    float sum = blockReduceSum(s, sdata);
    float sumsq = blockReduceSum(sq, sdata);
    float mu = sum / DMODEL;
    float var = sumsq / DMODEL - mu * mu;
    float rs = rsqrtf(var + 1e-12f);
    #pragma unroll
    for (int i = 0; i < 2; ++i) {
        int j = tid + i * 256;
        out[base + j] = (v[i] - mu) * rs * w[j] + bln[j];
    }
}

// ---------------- launch -----------------------------------------------------
extern "C" void kernel_launch(void* const* d_in, const int* in_sizes, int n_in,
                              void* d_out, int out_size)
{
    const float* item_emb   = (const float*)d_in[0];
    const float* in_proj_w  = (const float*)d_in[3];
    const float* conv_w     = (const float*)d_in[4];
    const float* conv_b     = (const float*)d_in[5];
    const float* dt_bias    = (const float*)d_in[6];
    const float* A_log      = (const float*)d_in[7];
    const float* Dp         = (const float*)d_in[8];
    const float* norm_w     = (const float*)d_in[9];
    const float* out_proj_w = (const float*)d_in[10];
    const float* ln_w       = (const float*)d_in[11];
    const float* ln_b       = (const float*)d_in[12];
    const float* ffn_w1     = (const float*)d_in[13];
    const float* ffn_b1     = (const float*)d_in[14];
    const float* ffn_w2     = (const float*)d_in[15];
    const float* ffn_b2     = (const float*)d_in[16];
    const float* ffn_ln_w   = (const float*)d_in[17];
    const float* ffn_ln_b   = (const float*)d_in[18];
    float* out = (float*)d_out;

    float *p_O, *p_H2;
    __half *p_zxh, *p_embh, *p_Gh, *p_Xh, *p_H1h, *p_winh, *p_wouth, *p_w1h, *p_w2h;
    cudaGetSymbolAddress((void**)&p_zxh,  g_zxh);
    cudaGetSymbolAddress((void**)&p_O,    g_O);
    cudaGetSymbolAddress((void**)&p_H2,   g_H2);
    cudaGetSymbolAddress((void**)&p_embh, g_emb_h);
    cudaGetSymbolAddress((void**)&p_Gh,   g_Gh);
    cudaGetSymbolAddress((void**)&p_Xh,   g_Xh);
    cudaGetSymbolAddress((void**)&p_H1h,  g_H1h);
    cudaGetSymbolAddress((void**)&p_winh, g_win_h);
    cudaGetSymbolAddress((void**)&p_wouth,g_wout_h);
    cudaGetSymbolAddress((void**)&p_w1h,  g_w1_h);
    cudaGetSymbolAddress((void**)&p_w2h,  g_w2_h);

    cudaFuncSetAttribute(h16gemm<0,0>, cudaFuncAttributeMaxDynamicSharedMemorySize, GEMM_SMEM);
    cudaFuncSetAttribute(h16gemm<0,1>, cudaFuncAttributeMaxDynamicSharedMemorySize, GEMM_SMEM);
    cudaFuncSetAttribute(h16gemm<2,1>, cudaFuncAttributeMaxDynamicSharedMemorySize, GEMM_SMEM);
    cudaFuncSetAttribute(h16gemm<1,0>, cudaFuncAttributeMaxDynamicSharedMemorySize, GEMM_SMEM);

    // 0) all fp16 conversions in ONE launch
    cvt_all_kernel<<<(Q_TOT + 255) / 256, 256>>>(item_emb, in_proj_w, out_proj_w,
                                                 ffn_w1, ffn_w2);

    // 1) in_proj (8192 x 2192 x 512) -> fp16
    {
        dim3 grid(DINPROJ_PAD / 128, NTOK / 128);
        h16gemm<0,1><<<grid, 256, GEMM_SMEM>>>(p_embh, p_winh, nullptr, p_zxh, NTOK, DINPROJ, DMODEL);
    }

    // 2+3) conv + silu + dt (fused)
    conv_dt_kernel<<<CONV_BLOCKS + DT_BLOCKS, 256>>>(conv_w, conv_b, dt_bias, A_log);

    // 4) SSD: chunk GEMMs, combine, fixup
    ssd_chunk_mma_kernel<<<2*BATCH*NHEADS*NCHUNK, 128>>>(Dp);
    ssd_combine_kernel<<<256, 64>>>();
    ssd_fixup_mma_kernel<<<2*BATCH*NHEADS*(NCHUNK-1), 128>>>();

    // 5) gate + RMS + combine -> fp16 G
    gate_rms_combine_kernel<<<NTOK, 256>>>(norm_w);

    // 6) out_proj (8192 x 512 x 1024)
    {
        dim3 grid(DMODEL / 128, NTOK / 128);
        h16gemm<0,0><<<grid, 256, GEMM_SMEM>>>(p_Gh, p_wouth, nullptr, p_O, NTOK, DMODEL, DINNER);
    }

    // 7) LN1
    ln1_kernel<<<NTOK, 256>>>(item_emb, ln_w, ln_b);

    // 8) FFN1 (8192 x 2048 x 512)
    {
        dim3 grid(DFFN / 128, NTOK / 128);
        h16gemm<2,1><<<grid, 256, GEMM_SMEM>>>(p_Xh, p_w1h, ffn_b1, p_H1h, NTOK, DFFN, DMODEL);
    }

    // 9) FFN2 (8192 x 512 x 2048)
    {
        dim3 grid(DMODEL / 128, NTOK / 128);
        h16gemm<1,0><<<grid, 256, GEMM_SMEM>>>(p_H1h, p_w2h, ffn_b2, p_H2, NTOK, DMODEL, DFFN);
    }

    // 10) final LN
    ln2_kernel<<<NTOK, 256>>>(out, ffn_ln_w, ffn_ln_b);
}